// round 1
// baseline (speedup 1.0000x reference)
#include <cuda_runtime.h>
#include <cuda_bf16.h>
#include <math.h>

// Problem constants
#define BB 2
#define TT 2048
#define DD 2048
#define HH 32
#define KVH 8
#define HDIM 64
#define GG 4                  // HH / KVH
#define NQKV 3072             // HH*HDIM + 2*KVH*HDIM
#define MM (BB*TT)            // 4096

// ---------------- scratch (device globals; no allocation allowed) ----------
__device__ float g_qkv[MM * NQKV];                       // 50 MB
__device__ float g_q[(size_t)BB * HH * TT * HDIM];       // 33.5 MB
__device__ float g_k[(size_t)BB * KVH * TT * HDIM];      // 8.4 MB
__device__ float g_v[(size_t)BB * KVH * TT * HDIM];      // 8.4 MB
__device__ float g_attn[(size_t)MM * DD];                // 33.5 MB

// ---------------------------------------------------------------------------
// SGEMM: C[M,N] = A[M,K] @ B[K,N], 128x128 block tile, BK=16, 256 threads,
// 8x8 per-thread microtile. EPI=1 adds bias + nan_to_num clamp.
// ---------------------------------------------------------------------------
__device__ __forceinline__ float nan_clamp(float x) {
    if (isnan(x)) return 0.0f;
    if (isinf(x)) return x > 0.0f ? 10000.0f : -10000.0f;
    return x;
}

template <int EPI>
__global__ void __launch_bounds__(256) sgemm_kernel(
    const float* __restrict__ A, const float* __restrict__ Bm,
    float* __restrict__ C, const float* __restrict__ bias,
    int Md, int Nd, int Kd)
{
    __shared__ float As[16][132];   // [k][m], padded stride
    __shared__ float Bs[16][128];   // [k][n]

    const int tid = threadIdx.x;
    const int tx = tid & 15;
    const int ty = tid >> 4;
    const int m0 = blockIdx.y * 128;
    const int n0 = blockIdx.x * 128;

    float acc[8][8];
#pragma unroll
    for (int i = 0; i < 8; i++)
#pragma unroll
        for (int j = 0; j < 8; j++) acc[i][j] = 0.0f;

    for (int k0 = 0; k0 < Kd; k0 += 16) {
        // Load A tile 128x16 (transposed store into As[k][m])
#pragma unroll
        for (int it = 0; it < 2; it++) {
            int idx = tid + it * 256;       // 0..511
            int row = idx >> 2;             // 0..127
            int q   = idx & 3;              // float4 index within 16 k's
            float4 av = *(const float4*)&A[(size_t)(m0 + row) * Kd + k0 + q * 4];
            As[q * 4 + 0][row] = av.x;
            As[q * 4 + 1][row] = av.y;
            As[q * 4 + 2][row] = av.z;
            As[q * 4 + 3][row] = av.w;
        }
        // Load B tile 16x128
#pragma unroll
        for (int it = 0; it < 2; it++) {
            int idx = tid + it * 256;       // 0..511
            int row = idx >> 5;             // 0..15
            int q   = idx & 31;             // 0..31
            *(float4*)&Bs[row][q * 4] =
                *(const float4*)&Bm[(size_t)(k0 + row) * Nd + n0 + q * 4];
        }
        __syncthreads();

#pragma unroll
        for (int kk = 0; kk < 16; kk++) {
            float4 a0 = *(float4*)&As[kk][ty * 4];
            float4 a1 = *(float4*)&As[kk][64 + ty * 4];
            float4 b0 = *(float4*)&Bs[kk][tx * 4];
            float4 b1 = *(float4*)&Bs[kk][64 + tx * 4];
            float a[8] = {a0.x, a0.y, a0.z, a0.w, a1.x, a1.y, a1.z, a1.w};
            float b[8] = {b0.x, b0.y, b0.z, b0.w, b1.x, b1.y, b1.z, b1.w};
#pragma unroll
            for (int i = 0; i < 8; i++)
#pragma unroll
                for (int j = 0; j < 8; j++)
                    acc[i][j] += a[i] * b[j];
        }
        __syncthreads();
    }

    // Epilogue
#pragma unroll
    for (int i = 0; i < 8; i++) {
        int rm = m0 + ((i < 4) ? (ty * 4 + i) : (64 + ty * 4 + (i - 4)));
#pragma unroll
        for (int jb = 0; jb < 2; jb++) {
            int cn = n0 + jb * 64 + tx * 4;
            float4 v;
            v.x = acc[i][jb * 4 + 0];
            v.y = acc[i][jb * 4 + 1];
            v.z = acc[i][jb * 4 + 2];
            v.w = acc[i][jb * 4 + 3];
            if (EPI) {
                v.x = nan_clamp(v.x + bias[cn + 0]);
                v.y = nan_clamp(v.y + bias[cn + 1]);
                v.z = nan_clamp(v.z + bias[cn + 2]);
                v.w = nan_clamp(v.w + bias[cn + 3]);
            }
            *(float4*)&C[(size_t)rm * Nd + cn] = v;
        }
    }
}

// ---------------------------------------------------------------------------
// RoPE + split qkv into head-major q [B,H,T,HD], k/v [B,KVH,T,HD]
// One thread per (even,odd) pair.
// ---------------------------------------------------------------------------
__global__ void rope_split_kernel(
    const float* __restrict__ qkv,
    const float* __restrict__ rcos, const float* __restrict__ rsin,
    float* __restrict__ q, float* __restrict__ k, float* __restrict__ v)
{
    int idx = blockIdx.x * blockDim.x + threadIdx.x;
    const int TOT = MM * (NQKV / 2);
    if (idx >= TOT) return;
    int m  = idx / (NQKV / 2);
    int c2 = idx - m * (NQKV / 2);
    int c  = c2 * 2;
    int b = m >> 11;          // m / TT
    int t = m & (TT - 1);

    float e = qkv[(size_t)m * NQKV + c];
    float o = qkv[(size_t)m * NQKV + c + 1];
    int d = c & (HDIM - 1);
    int i = d >> 1;

    if (c < HH * HDIM) {
        int h = c >> 6;
        float cs = rcos[t * (HDIM / 2) + i];
        float sn = rsin[t * (HDIM / 2) + i];
        size_t base = (((size_t)b * HH + h) * TT + t) * HDIM + d;
        q[base]     = e * cs - o * sn;
        q[base + 1] = e * sn + o * cs;
    } else if (c < HH * HDIM + KVH * HDIM) {
        int kh = (c - HH * HDIM) >> 6;
        float cs = rcos[t * (HDIM / 2) + i];
        float sn = rsin[t * (HDIM / 2) + i];
        size_t base = (((size_t)b * KVH + kh) * TT + t) * HDIM + d;
        k[base]     = e * cs - o * sn;
        k[base + 1] = e * sn + o * cs;
    } else {
        int kh = (c - HH * HDIM - KVH * HDIM) >> 6;
        size_t base = (((size_t)b * KVH + kh) * TT + t) * HDIM + d;
        v[base]     = e;
        v[base + 1] = o;
    }
}

// ---------------------------------------------------------------------------
// Causal flash attention, fp32. 64x64 tiles, HD=64.
// grid: (T/64, B*H). block: 256 threads = 16x16; each thread owns 4x4 of S/O.
// Writes output in [b, t, h*HD + d] layout (ready for out-projection).
// ---------------------------------------------------------------------------
#define FS 68   // smem row stride (floats)

__global__ void __launch_bounds__(256) flash_kernel(
    const float* __restrict__ Q, const float* __restrict__ K,
    const float* __restrict__ V, float* __restrict__ Ob)
{
    extern __shared__ float sm[];
    float* Qs = sm;
    float* Ks = sm + 64 * FS;
    float* Vs = sm + 2 * 64 * FS;
    float* Ps = sm + 3 * 64 * FS;

    const int qt = blockIdx.x;
    const int bh = blockIdx.y;
    const int b = bh / HH;
    const int h = bh - b * HH;
    const int kvh = h / GG;
    const int tid = threadIdx.x;
    const int tx = tid & 15;
    const int ty = tid >> 4;

    const float* qptr = Q + (((size_t)b * HH + h) * TT + (size_t)qt * 64) * HDIM;
    const float* kptr = K + (((size_t)b * KVH + kvh) * TT) * HDIM;
    const float* vptr = V + (((size_t)b * KVH + kvh) * TT) * HDIM;

    // Load Q tile (64 x 64)
#pragma unroll
    for (int it = 0; it < 4; it++) {
        int idx = tid + it * 256;     // 0..1023
        int row = idx >> 4;
        int qq  = idx & 15;
        *(float4*)&Qs[row * FS + qq * 4] = *(const float4*)&qptr[row * 64 + qq * 4];
    }

    float m_i[4], l_i[4], o[4][4];
#pragma unroll
    for (int i = 0; i < 4; i++) {
        m_i[i] = -1e30f; l_i[i] = 0.0f;
#pragma unroll
        for (int j = 0; j < 4; j++) o[i][j] = 0.0f;
    }

    const float scale = 0.125f;   // 1/sqrt(64)

    for (int kt = 0; kt <= qt; kt++) {
        __syncthreads();   // prior Ps/Vs reads done before overwrite (also orders Qs stores)
        // Load K,V tiles
#pragma unroll
        for (int it = 0; it < 4; it++) {
            int idx = tid + it * 256;
            int row = idx >> 4;
            int qq  = idx & 15;
            *(float4*)&Ks[row * FS + qq * 4] =
                *(const float4*)&kptr[((size_t)kt * 64 + row) * 64 + qq * 4];
            *(float4*)&Vs[row * FS + qq * 4] =
                *(const float4*)&vptr[((size_t)kt * 64 + row) * 64 + qq * 4];
        }
        __syncthreads();

        // S = Q K^T
        float s[4][4];
#pragma unroll
        for (int i = 0; i < 4; i++)
#pragma unroll
            for (int j = 0; j < 4; j++) s[i][j] = 0.0f;

#pragma unroll
        for (int d4 = 0; d4 < 16; d4++) {
            float4 qa[4], ka[4];
#pragma unroll
            for (int i = 0; i < 4; i++) qa[i] = *(float4*)&Qs[(ty * 4 + i) * FS + d4 * 4];
#pragma unroll
            for (int j = 0; j < 4; j++) ka[j] = *(float4*)&Ks[(tx * 4 + j) * FS + d4 * 4];
#pragma unroll
            for (int i = 0; i < 4; i++)
#pragma unroll
                for (int j = 0; j < 4; j++) {
                    s[i][j] += qa[i].x * ka[j].x;
                    s[i][j] += qa[i].y * ka[j].y;
                    s[i][j] += qa[i].z * ka[j].z;
                    s[i][j] += qa[i].w * ka[j].w;
                }
        }

        // scale + causal mask (only diagonal tile needs masking)
        if (kt == qt) {
#pragma unroll
            for (int i = 0; i < 4; i++)
#pragma unroll
                for (int j = 0; j < 4; j++) {
                    if (tx * 4 + j > ty * 4 + i) s[i][j] = -1e30f;
                    else s[i][j] *= scale;
                }
        } else {
#pragma unroll
            for (int i = 0; i < 4; i++)
#pragma unroll
                for (int j = 0; j < 4; j++) s[i][j] *= scale;
        }

        // online softmax update
#pragma unroll
        for (int i = 0; i < 4; i++) {
            float rm = s[i][0];
            rm = fmaxf(rm, s[i][1]); rm = fmaxf(rm, s[i][2]); rm = fmaxf(rm, s[i][3]);
#pragma unroll
            for (int off = 8; off >= 1; off >>= 1)
                rm = fmaxf(rm, __shfl_xor_sync(0xffffffffu, rm, off));
            float newm = fmaxf(m_i[i], rm);
            float alpha = __expf(m_i[i] - newm);
            m_i[i] = newm;
            float rs = 0.0f;
#pragma unroll
            for (int j = 0; j < 4; j++) {
                float p = __expf(s[i][j] - newm);
                s[i][j] = p;
                rs += p;
            }
#pragma unroll
            for (int off = 8; off >= 1; off >>= 1)
                rs += __shfl_xor_sync(0xffffffffu, rs, off);
            l_i[i] = l_i[i] * alpha + rs;
#pragma unroll
            for (int j = 0; j < 4; j++) o[i][j] *= alpha;
        }

        // store P to smem
#pragma unroll
        for (int i = 0; i < 4; i++) {
            float4 pv;
            pv.x = s[i][0]; pv.y = s[i][1]; pv.z = s[i][2]; pv.w = s[i][3];
            *(float4*)&Ps[(ty * 4 + i) * FS + tx * 4] = pv;
        }
        __syncthreads();

        // O += P @ V
#pragma unroll 8
        for (int key = 0; key < 64; key++) {
            float4 vv = *(float4*)&Vs[key * FS + tx * 4];
#pragma unroll
            for (int i = 0; i < 4; i++) {
                float p = Ps[(ty * 4 + i) * FS + key];
                o[i][0] += p * vv.x;
                o[i][1] += p * vv.y;
                o[i][2] += p * vv.z;
                o[i][3] += p * vv.w;
            }
        }
    }

    // finalize + write [b, t, h*HD + d]
#pragma unroll
    for (int i = 0; i < 4; i++) {
        float inv = 1.0f / l_i[i];
        int r = ty * 4 + i;
        float4 v;
        v.x = o[i][0] * inv; v.y = o[i][1] * inv;
        v.z = o[i][2] * inv; v.w = o[i][3] * inv;
        size_t row = (size_t)b * TT + (size_t)qt * 64 + r;
        *(float4*)&Ob[row * DD + h * HDIM + tx * 4] = v;
    }
}

// ---------------------------------------------------------------------------
extern "C" void kernel_launch(void* const* d_in, const int* in_sizes, int n_in,
                              void* d_out, int out_size)
{
    const float* x    = (const float*)d_in[0];
    const float* Wqkv = (const float*)d_in[1];
    const float* Wout = (const float*)d_in[2];
    const float* bout = (const float*)d_in[3];
    const float* rcos = (const float*)d_in[4];
    const float* rsin = (const float*)d_in[5];
    float* out = (float*)d_out;

    float *qkv, *q, *k, *v, *attn;
    cudaGetSymbolAddress((void**)&qkv,  g_qkv);
    cudaGetSymbolAddress((void**)&q,    g_q);
    cudaGetSymbolAddress((void**)&k,    g_k);
    cudaGetSymbolAddress((void**)&v,    g_v);
    cudaGetSymbolAddress((void**)&attn, g_attn);

    // 1. QKV projection: [4096,2048] @ [2048,3072]
    {
        dim3 grid(NQKV / 128, MM / 128);
        sgemm_kernel<0><<<grid, 256>>>(x, Wqkv, qkv, nullptr, MM, NQKV, DD);
    }

    // 2. RoPE + split into head-major q/k/v
    {
        int tot = MM * (NQKV / 2);
        rope_split_kernel<<<(tot + 255) / 256, 256>>>(qkv, rcos, rsin, q, k, v);
    }

    // 3. Causal flash attention
    {
        int smem = 4 * 64 * FS * sizeof(float);   // 69632 B
        cudaFuncSetAttribute(flash_kernel, cudaFuncAttributeMaxDynamicSharedMemorySize, smem);
        dim3 grid(TT / 64, BB * HH);
        flash_kernel<<<grid, 256, smem>>>(q, k, v, attn);
    }

    // 4. Out projection + bias + nan_to_num: [4096,2048] @ [2048,2048]
    {
        dim3 grid(DD / 128, MM / 128);
        sgemm_kernel<1><<<grid, 256>>>(attn, Wout, out, bout, MM, DD, DD);
    }
}

// round 3
// speedup vs baseline: 1.4955x; 1.4955x over previous
#include <cuda_runtime.h>
#include <cuda_bf16.h>
#include <math.h>
#include <stdint.h>

// Problem constants
#define BB 2
#define TT 2048
#define DD 2048
#define HH 32
#define KVH 8
#define HDIM 64
#define GG 4                  // HH / KVH
#define NQKV 3072             // HH*HDIM + 2*KVH*HDIM
#define MM (BB*TT)            // 4096

// ---------------- scratch (device globals; no allocation allowed) ----------
__device__ float g_qkv[MM * NQKV];                       // 50 MB
__device__ float g_q[(size_t)BB * HH * TT * HDIM];       // 33.5 MB
__device__ float g_k[(size_t)BB * KVH * TT * HDIM];      // 8.4 MB
__device__ float g_v[(size_t)BB * KVH * TT * HDIM];      // 8.4 MB
__device__ float g_attn[(size_t)MM * DD];                // 33.5 MB

__device__ __forceinline__ float nan_clamp(float x) {
    if (isnan(x)) return 0.0f;
    if (isinf(x)) return x > 0.0f ? 10000.0f : -10000.0f;
    return x;
}

__device__ __forceinline__ float to_tf32(float x) {
    uint32_t u;
    asm("cvt.rna.tf32.f32 %0, %1;" : "=r"(u) : "f"(x));
    return __uint_as_float(u);
}

__device__ __forceinline__ void mma_tf32(float& c0, float& c1, float& c2, float& c3,
                                         uint32_t a0, uint32_t a1, uint32_t a2, uint32_t a3,
                                         uint32_t b0, uint32_t b1) {
    asm volatile(
        "mma.sync.aligned.m16n8k8.row.col.f32.tf32.tf32.f32 "
        "{%0,%1,%2,%3}, {%4,%5,%6,%7}, {%8,%9}, {%0,%1,%2,%3};\n"
        : "+f"(c0), "+f"(c1), "+f"(c2), "+f"(c3)
        : "r"(a0), "r"(a1), "r"(a2), "r"(a3), "r"(b0), "r"(b1));
}

// ---------------------------------------------------------------------------
// TF32 tensor-core GEMM: C[M,N] = A[M,K] @ B[K,N]
// 128x128 CTA tile, BK=32, 256 threads = 8 warps (2 m x 4 n), 64x32 warp tile.
// As: [m][k] stride 36 (frag-load banks 4g+t -> conflict-free)
// Bs: [k][n] stride 136 (frag-load banks 8t+g -> conflict-free)
// EPI=1 adds bias + nan_to_num clamp.
// ---------------------------------------------------------------------------
#define AS_S 36
#define BS_S 136

template <int EPI>
__global__ void __launch_bounds__(256) mma_gemm_kernel(
    const float* __restrict__ A, const float* __restrict__ Bm,
    float* __restrict__ C, const float* __restrict__ bias,
    int Md, int Nd, int Kd)
{
    __shared__ float As[128 * AS_S];   // 18432 B
    __shared__ float Bs[32 * BS_S];    // 17408 B

    const int tid = threadIdx.x;
    const int m0 = blockIdx.y * 128;
    const int n0 = blockIdx.x * 128;

    const int w  = tid >> 5;
    const int l  = tid & 31;
    const int wm = (w >> 2) * 64;      // 0 or 64
    const int wn = (w & 3) * 32;       // 0,32,64,96
    const int g  = l >> 2;             // 0..7
    const int t4 = l & 3;              // 0..3

    float acc[4][4][4];
#pragma unroll
    for (int mt = 0; mt < 4; mt++)
#pragma unroll
        for (int nt = 0; nt < 4; nt++)
#pragma unroll
            for (int r = 0; r < 4; r++) acc[mt][nt][r] = 0.0f;

    for (int k0 = 0; k0 < Kd; k0 += 32) {
        // ---- load A tile 128x32 -> As[m][k], tf32-rounded ----
#pragma unroll
        for (int it = 0; it < 4; it++) {
            int idx = tid + it * 256;          // 0..1023
            int m   = idx >> 3;                // 0..127
            int kq  = idx & 7;                 // 0..7
            float4 av = *(const float4*)&A[(size_t)(m0 + m) * Kd + k0 + kq * 4];
            av.x = to_tf32(av.x); av.y = to_tf32(av.y);
            av.z = to_tf32(av.z); av.w = to_tf32(av.w);
            *(float4*)&As[m * AS_S + kq * 4] = av;
        }
        // ---- load B tile 32x128 -> Bs[k][n], tf32-rounded ----
#pragma unroll
        for (int it = 0; it < 4; it++) {
            int idx = tid + it * 256;          // 0..1023
            int kb  = idx >> 5;                // 0..31
            int nq  = idx & 31;                // 0..31
            float4 bv = *(const float4*)&Bm[(size_t)(k0 + kb) * Nd + n0 + nq * 4];
            bv.x = to_tf32(bv.x); bv.y = to_tf32(bv.y);
            bv.z = to_tf32(bv.z); bv.w = to_tf32(bv.w);
            *(float4*)&Bs[kb * BS_S + nq * 4] = bv;
        }
        __syncthreads();

#pragma unroll
        for (int ks = 0; ks < 4; ks++) {
            const int kb = ks * 8;
            uint32_t af[4][4], bf[4][2];
#pragma unroll
            for (int mt = 0; mt < 4; mt++) {
                int bm = wm + mt * 16;
                af[mt][0] = __float_as_uint(As[(bm + g)     * AS_S + kb + t4]);
                af[mt][1] = __float_as_uint(As[(bm + g + 8) * AS_S + kb + t4]);
                af[mt][2] = __float_as_uint(As[(bm + g)     * AS_S + kb + t4 + 4]);
                af[mt][3] = __float_as_uint(As[(bm + g + 8) * AS_S + kb + t4 + 4]);
            }
#pragma unroll
            for (int nt = 0; nt < 4; nt++) {
                int bn = wn + nt * 8;
                bf[nt][0] = __float_as_uint(Bs[(kb + t4)     * BS_S + bn + g]);
                bf[nt][1] = __float_as_uint(Bs[(kb + t4 + 4) * BS_S + bn + g]);
            }
#pragma unroll
            for (int mt = 0; mt < 4; mt++)
#pragma unroll
                for (int nt = 0; nt < 4; nt++)
                    mma_tf32(acc[mt][nt][0], acc[mt][nt][1], acc[mt][nt][2], acc[mt][nt][3],
                             af[mt][0], af[mt][1], af[mt][2], af[mt][3],
                             bf[nt][0], bf[nt][1]);
        }
        __syncthreads();
    }

    // ---- epilogue: c0,c1 @ (row g, col 2t), c2,c3 @ (row g+8, col 2t) ----
#pragma unroll
    for (int mt = 0; mt < 4; mt++) {
#pragma unroll
        for (int nt = 0; nt < 4; nt++) {
            int row = m0 + wm + mt * 16 + g;
            int col = n0 + wn + nt * 8 + 2 * t4;
            float2 v0 = make_float2(acc[mt][nt][0], acc[mt][nt][1]);
            float2 v1 = make_float2(acc[mt][nt][2], acc[mt][nt][3]);
            if (EPI) {
                v0.x = nan_clamp(v0.x + bias[col]);
                v0.y = nan_clamp(v0.y + bias[col + 1]);
                v1.x = nan_clamp(v1.x + bias[col]);
                v1.y = nan_clamp(v1.y + bias[col + 1]);
            }
            *(float2*)&C[(size_t)row * Nd + col]       = v0;
            *(float2*)&C[(size_t)(row + 8) * Nd + col] = v1;
        }
    }
}

// ---------------------------------------------------------------------------
// RoPE + split qkv into head-major q [B,H,T,HD], k/v [B,KVH,T,HD]
// ---------------------------------------------------------------------------
__global__ void rope_split_kernel(
    const float* __restrict__ qkv,
    const float* __restrict__ rcos, const float* __restrict__ rsin,
    float* __restrict__ q, float* __restrict__ k, float* __restrict__ v)
{
    int idx = blockIdx.x * blockDim.x + threadIdx.x;
    const int TOT = MM * (NQKV / 2);
    if (idx >= TOT) return;
    int m  = idx / (NQKV / 2);
    int c2 = idx - m * (NQKV / 2);
    int c  = c2 * 2;
    int b = m >> 11;
    int t = m & (TT - 1);

    float e = qkv[(size_t)m * NQKV + c];
    float o = qkv[(size_t)m * NQKV + c + 1];
    int d = c & (HDIM - 1);
    int i = d >> 1;

    if (c < HH * HDIM) {
        int h = c >> 6;
        float cs = rcos[t * (HDIM / 2) + i];
        float sn = rsin[t * (HDIM / 2) + i];
        size_t base = (((size_t)b * HH + h) * TT + t) * HDIM + d;
        q[base]     = e * cs - o * sn;
        q[base + 1] = e * sn + o * cs;
    } else if (c < HH * HDIM + KVH * HDIM) {
        int kh = (c - HH * HDIM) >> 6;
        float cs = rcos[t * (HDIM / 2) + i];
        float sn = rsin[t * (HDIM / 2) + i];
        size_t base = (((size_t)b * KVH + kh) * TT + t) * HDIM + d;
        k[base]     = e * cs - o * sn;
        k[base + 1] = e * sn + o * cs;
    } else {
        int kh = (c - HH * HDIM - KVH * HDIM) >> 6;
        size_t base = (((size_t)b * KVH + kh) * TT + t) * HDIM + d;
        v[base]     = e;
        v[base + 1] = o;
    }
}

// ---------------------------------------------------------------------------
// Causal flash attention, fp32 (unchanged this round; next target).
// ---------------------------------------------------------------------------
#define FS 68

__global__ void __launch_bounds__(256) flash_kernel(
    const float* __restrict__ Q, const float* __restrict__ K,
    const float* __restrict__ V, float* __restrict__ Ob)
{
    extern __shared__ float sm[];
    float* Qs = sm;
    float* Ks = sm + 64 * FS;
    float* Vs = sm + 2 * 64 * FS;
    float* Ps = sm + 3 * 64 * FS;

    const int qt = blockIdx.x;
    const int bh = blockIdx.y;
    const int b = bh / HH;
    const int h = bh - b * HH;
    const int kvh = h / GG;
    const int tid = threadIdx.x;
    const int tx = tid & 15;
    const int ty = tid >> 4;

    const float* qptr = Q + (((size_t)b * HH + h) * TT + (size_t)qt * 64) * HDIM;
    const float* kptr = K + (((size_t)b * KVH + kvh) * TT) * HDIM;
    const float* vptr = V + (((size_t)b * KVH + kvh) * TT) * HDIM;

#pragma unroll
    for (int it = 0; it < 4; it++) {
        int idx = tid + it * 256;
        int row = idx >> 4;
        int qq  = idx & 15;
        *(float4*)&Qs[row * FS + qq * 4] = *(const float4*)&qptr[row * 64 + qq * 4];
    }

    float m_i[4], l_i[4], o[4][4];
#pragma unroll
    for (int i = 0; i < 4; i++) {
        m_i[i] = -1e30f; l_i[i] = 0.0f;
#pragma unroll
        for (int j = 0; j < 4; j++) o[i][j] = 0.0f;
    }

    const float scale = 0.125f;

    for (int kt = 0; kt <= qt; kt++) {
        __syncthreads();
#pragma unroll
        for (int it = 0; it < 4; it++) {
            int idx = tid + it * 256;
            int row = idx >> 4;
            int qq  = idx & 15;
            *(float4*)&Ks[row * FS + qq * 4] =
                *(const float4*)&kptr[((size_t)kt * 64 + row) * 64 + qq * 4];
            *(float4*)&Vs[row * FS + qq * 4] =
                *(const float4*)&vptr[((size_t)kt * 64 + row) * 64 + qq * 4];
        }
        __syncthreads();

        float s[4][4];
#pragma unroll
        for (int i = 0; i < 4; i++)
#pragma unroll
            for (int j = 0; j < 4; j++) s[i][j] = 0.0f;

#pragma unroll
        for (int d4 = 0; d4 < 16; d4++) {
            float4 qa[4], ka[4];
#pragma unroll
            for (int i = 0; i < 4; i++) qa[i] = *(float4*)&Qs[(ty * 4 + i) * FS + d4 * 4];
#pragma unroll
            for (int j = 0; j < 4; j++) ka[j] = *(float4*)&Ks[(tx * 4 + j) * FS + d4 * 4];
#pragma unroll
            for (int i = 0; i < 4; i++)
#pragma unroll
                for (int j = 0; j < 4; j++) {
                    s[i][j] += qa[i].x * ka[j].x;
                    s[i][j] += qa[i].y * ka[j].y;
                    s[i][j] += qa[i].z * ka[j].z;
                    s[i][j] += qa[i].w * ka[j].w;
                }
        }

        if (kt == qt) {
#pragma unroll
            for (int i = 0; i < 4; i++)
#pragma unroll
                for (int j = 0; j < 4; j++) {
                    if (tx * 4 + j > ty * 4 + i) s[i][j] = -1e30f;
                    else s[i][j] *= scale;
                }
        } else {
#pragma unroll
            for (int i = 0; i < 4; i++)
#pragma unroll
                for (int j = 0; j < 4; j++) s[i][j] *= scale;
        }

#pragma unroll
        for (int i = 0; i < 4; i++) {
            float rm = s[i][0];
            rm = fmaxf(rm, s[i][1]); rm = fmaxf(rm, s[i][2]); rm = fmaxf(rm, s[i][3]);
#pragma unroll
            for (int off = 8; off >= 1; off >>= 1)
                rm = fmaxf(rm, __shfl_xor_sync(0xffffffffu, rm, off));
            float newm = fmaxf(m_i[i], rm);
            float alpha = __expf(m_i[i] - newm);
            m_i[i] = newm;
            float rs = 0.0f;
#pragma unroll
            for (int j = 0; j < 4; j++) {
                float p = __expf(s[i][j] - newm);
                s[i][j] = p;
                rs += p;
            }
#pragma unroll
            for (int off = 8; off >= 1; off >>= 1)
                rs += __shfl_xor_sync(0xffffffffu, rs, off);
            l_i[i] = l_i[i] * alpha + rs;
#pragma unroll
            for (int j = 0; j < 4; j++) o[i][j] *= alpha;
        }

#pragma unroll
        for (int i = 0; i < 4; i++) {
            float4 pv;
            pv.x = s[i][0]; pv.y = s[i][1]; pv.z = s[i][2]; pv.w = s[i][3];
            *(float4*)&Ps[(ty * 4 + i) * FS + tx * 4] = pv;
        }
        __syncthreads();

#pragma unroll 8
        for (int key = 0; key < 64; key++) {
            float4 vv = *(float4*)&Vs[key * FS + tx * 4];
#pragma unroll
            for (int i = 0; i < 4; i++) {
                float p = Ps[(ty * 4 + i) * FS + key];
                o[i][0] += p * vv.x;
                o[i][1] += p * vv.y;
                o[i][2] += p * vv.z;
                o[i][3] += p * vv.w;
            }
        }
    }

#pragma unroll
    for (int i = 0; i < 4; i++) {
        float inv = 1.0f / l_i[i];
        int r = ty * 4 + i;
        float4 v;
        v.x = o[i][0] * inv; v.y = o[i][1] * inv;
        v.z = o[i][2] * inv; v.w = o[i][3] * inv;
        size_t row = (size_t)b * TT + (size_t)qt * 64 + r;
        *(float4*)&Ob[row * DD + h * HDIM + tx * 4] = v;
    }
}

// ---------------------------------------------------------------------------
extern "C" void kernel_launch(void* const* d_in, const int* in_sizes, int n_in,
                              void* d_out, int out_size)
{
    const float* x    = (const float*)d_in[0];
    const float* Wqkv = (const float*)d_in[1];
    const float* Wout = (const float*)d_in[2];
    const float* bout = (const float*)d_in[3];
    const float* rcos = (const float*)d_in[4];
    const float* rsin = (const float*)d_in[5];
    float* out = (float*)d_out;

    float *qkv, *q, *k, *v, *attn;
    cudaGetSymbolAddress((void**)&qkv,  g_qkv);
    cudaGetSymbolAddress((void**)&q,    g_q);
    cudaGetSymbolAddress((void**)&k,    g_k);
    cudaGetSymbolAddress((void**)&v,    g_v);
    cudaGetSymbolAddress((void**)&attn, g_attn);

    // 1. QKV projection: [4096,2048] @ [2048,3072]  (tf32 tensor cores)
    {
        dim3 grid(NQKV / 128, MM / 128);
        mma_gemm_kernel<0><<<grid, 256>>>(x, Wqkv, qkv, nullptr, MM, NQKV, DD);
    }

    // 2. RoPE + split into head-major q/k/v
    {
        int tot = MM * (NQKV / 2);
        rope_split_kernel<<<(tot + 255) / 256, 256>>>(qkv, rcos, rsin, q, k, v);
    }

    // 3. Causal flash attention
    {
        int smem = 4 * 64 * FS * sizeof(float);
        cudaFuncSetAttribute(flash_kernel, cudaFuncAttributeMaxDynamicSharedMemorySize, smem);
        dim3 grid(TT / 64, BB * HH);
        flash_kernel<<<grid, 256, smem>>>(q, k, v, attn);
    }

    // 4. Out projection + bias + nan_to_num  (tf32 tensor cores)
    {
        dim3 grid(DD / 128, MM / 128);
        mma_gemm_kernel<1><<<grid, 256>>>(attn, Wout, out, bout, MM, DD, DD);
    }
}

// round 5
// speedup vs baseline: 3.3155x; 2.2170x over previous
#include <cuda_runtime.h>
#include <cuda_bf16.h>
#include <math.h>
#include <stdint.h>

// Problem constants
#define BB 2
#define TT 2048
#define DD 2048
#define HH 32
#define KVH 8
#define HDIM 64
#define GG 4
#define NQKV 3072
#define MM (BB*TT)

// ---------------- scratch ----------
__device__ float g_qkv[MM * NQKV];
__device__ float g_q[(size_t)BB * HH * TT * HDIM];
__device__ float g_k[(size_t)BB * KVH * TT * HDIM];
__device__ float g_v[(size_t)BB * KVH * TT * HDIM];
__device__ float g_attn[(size_t)MM * DD];

__device__ __forceinline__ float nan_clamp(float x) {
    if (isnan(x)) return 0.0f;
    if (isinf(x)) return x > 0.0f ? 10000.0f : -10000.0f;
    return x;
}

__device__ __forceinline__ float to_tf32(float x) {
    uint32_t u;
    asm("cvt.rna.tf32.f32 %0, %1;" : "=r"(u) : "f"(x));
    return __uint_as_float(u);
}

__device__ __forceinline__ void mma_tf32(float& c0, float& c1, float& c2, float& c3,
                                         uint32_t a0, uint32_t a1, uint32_t a2, uint32_t a3,
                                         uint32_t b0, uint32_t b1) {
    asm volatile(
        "mma.sync.aligned.m16n8k8.row.col.f32.tf32.tf32.f32 "
        "{%0,%1,%2,%3}, {%4,%5,%6,%7}, {%8,%9}, {%0,%1,%2,%3};\n"
        : "+f"(c0), "+f"(c1), "+f"(c2), "+f"(c3)
        : "r"(a0), "r"(a1), "r"(a2), "r"(a3), "r"(b0), "r"(b1));
}

// ---------------------------------------------------------------------------
// TF32 tensor-core GEMM (unchanged from R2)
// ---------------------------------------------------------------------------
#define AS_S 36
#define BS_S 136

template <int EPI>
__global__ void __launch_bounds__(256) mma_gemm_kernel(
    const float* __restrict__ A, const float* __restrict__ Bm,
    float* __restrict__ C, const float* __restrict__ bias,
    int Md, int Nd, int Kd)
{
    __shared__ float As[128 * AS_S];
    __shared__ float Bs[32 * BS_S];

    const int tid = threadIdx.x;
    const int m0 = blockIdx.y * 128;
    const int n0 = blockIdx.x * 128;

    const int w  = tid >> 5;
    const int l  = tid & 31;
    const int wm = (w >> 2) * 64;
    const int wn = (w & 3) * 32;
    const int g  = l >> 2;
    const int t4 = l & 3;

    float acc[4][4][4];
#pragma unroll
    for (int mt = 0; mt < 4; mt++)
#pragma unroll
        for (int nt = 0; nt < 4; nt++)
#pragma unroll
            for (int r = 0; r < 4; r++) acc[mt][nt][r] = 0.0f;

    for (int k0 = 0; k0 < Kd; k0 += 32) {
#pragma unroll
        for (int it = 0; it < 4; it++) {
            int idx = tid + it * 256;
            int m   = idx >> 3;
            int kq  = idx & 7;
            float4 av = *(const float4*)&A[(size_t)(m0 + m) * Kd + k0 + kq * 4];
            av.x = to_tf32(av.x); av.y = to_tf32(av.y);
            av.z = to_tf32(av.z); av.w = to_tf32(av.w);
            *(float4*)&As[m * AS_S + kq * 4] = av;
        }
#pragma unroll
        for (int it = 0; it < 4; it++) {
            int idx = tid + it * 256;
            int kb  = idx >> 5;
            int nq  = idx & 31;
            float4 bv = *(const float4*)&Bm[(size_t)(k0 + kb) * Nd + n0 + nq * 4];
            bv.x = to_tf32(bv.x); bv.y = to_tf32(bv.y);
            bv.z = to_tf32(bv.z); bv.w = to_tf32(bv.w);
            *(float4*)&Bs[kb * BS_S + nq * 4] = bv;
        }
        __syncthreads();

#pragma unroll
        for (int ks = 0; ks < 4; ks++) {
            const int kb = ks * 8;
            uint32_t af[4][4], bf[4][2];
#pragma unroll
            for (int mt = 0; mt < 4; mt++) {
                int bm = wm + mt * 16;
                af[mt][0] = __float_as_uint(As[(bm + g)     * AS_S + kb + t4]);
                af[mt][1] = __float_as_uint(As[(bm + g + 8) * AS_S + kb + t4]);
                af[mt][2] = __float_as_uint(As[(bm + g)     * AS_S + kb + t4 + 4]);
                af[mt][3] = __float_as_uint(As[(bm + g + 8) * AS_S + kb + t4 + 4]);
            }
#pragma unroll
            for (int nt = 0; nt < 4; nt++) {
                int bn = wn + nt * 8;
                bf[nt][0] = __float_as_uint(Bs[(kb + t4)     * BS_S + bn + g]);
                bf[nt][1] = __float_as_uint(Bs[(kb + t4 + 4) * BS_S + bn + g]);
            }
#pragma unroll
            for (int mt = 0; mt < 4; mt++)
#pragma unroll
                for (int nt = 0; nt < 4; nt++)
                    mma_tf32(acc[mt][nt][0], acc[mt][nt][1], acc[mt][nt][2], acc[mt][nt][3],
                             af[mt][0], af[mt][1], af[mt][2], af[mt][3],
                             bf[nt][0], bf[nt][1]);
        }
        __syncthreads();
    }

#pragma unroll
    for (int mt = 0; mt < 4; mt++) {
#pragma unroll
        for (int nt = 0; nt < 4; nt++) {
            int row = m0 + wm + mt * 16 + g;
            int col = n0 + wn + nt * 8 + 2 * t4;
            float2 v0 = make_float2(acc[mt][nt][0], acc[mt][nt][1]);
            float2 v1 = make_float2(acc[mt][nt][2], acc[mt][nt][3]);
            if (EPI) {
                v0.x = nan_clamp(v0.x + bias[col]);
                v0.y = nan_clamp(v0.y + bias[col + 1]);
                v1.x = nan_clamp(v1.x + bias[col]);
                v1.y = nan_clamp(v1.y + bias[col + 1]);
            }
            *(float2*)&C[(size_t)row * Nd + col]       = v0;
            *(float2*)&C[(size_t)(row + 8) * Nd + col] = v1;
        }
    }
}

// ---------------------------------------------------------------------------
// RoPE + split (unchanged)
// ---------------------------------------------------------------------------
__global__ void rope_split_kernel(
    const float* __restrict__ qkv,
    const float* __restrict__ rcos, const float* __restrict__ rsin,
    float* __restrict__ q, float* __restrict__ k, float* __restrict__ v)
{
    int idx = blockIdx.x * blockDim.x + threadIdx.x;
    const int TOT = MM * (NQKV / 2);
    if (idx >= TOT) return;
    int m  = idx / (NQKV / 2);
    int c2 = idx - m * (NQKV / 2);
    int c  = c2 * 2;
    int b = m >> 11;
    int t = m & (TT - 1);

    float e = qkv[(size_t)m * NQKV + c];
    float o = qkv[(size_t)m * NQKV + c + 1];
    int d = c & (HDIM - 1);
    int i = d >> 1;

    if (c < HH * HDIM) {
        int h = c >> 6;
        float cs = rcos[t * (HDIM / 2) + i];
        float sn = rsin[t * (HDIM / 2) + i];
        size_t base = (((size_t)b * HH + h) * TT + t) * HDIM + d;
        q[base]     = e * cs - o * sn;
        q[base + 1] = e * sn + o * cs;
    } else if (c < HH * HDIM + KVH * HDIM) {
        int kh = (c - HH * HDIM) >> 6;
        float cs = rcos[t * (HDIM / 2) + i];
        float sn = rsin[t * (HDIM / 2) + i];
        size_t base = (((size_t)b * KVH + kh) * TT + t) * HDIM + d;
        k[base]     = e * cs - o * sn;
        k[base + 1] = e * sn + o * cs;
    } else {
        int kh = (c - HH * HDIM - KVH * HDIM) >> 6;
        size_t base = (((size_t)b * KVH + kh) * TT + t) * HDIM + d;
        v[base]     = e;
        v[base + 1] = o;
    }
}

// ---------------------------------------------------------------------------
// Causal flash attention on tf32 tensor cores.
// CTA: 128 q-rows x 64-key tiles. 8 warps; warp w owns rows w*16..w*16+15
// (full key range -> softmax reductions stay inside the t4 quad).
// S = Q K^T via mma(A=Qs[row][d], B=Ks[d][key]); P via smem; O += P V.
// ---------------------------------------------------------------------------
#define QS_S 68
#define KS_S 72
#define VS_S 72
#define PS_S 68

__global__ void __launch_bounds__(256) flash_kernel(
    const float* __restrict__ Q, const float* __restrict__ K,
    const float* __restrict__ V, float* __restrict__ Ob)
{
    extern __shared__ float sm[];
    float* Qs = sm;                              // 128*68
    float* Ks = Qs + 128 * QS_S;                 // 64*72  [d][key] (transposed)
    float* Vs = Ks + 64 * KS_S;                  // 64*72  [key][d]
    float* Ps = Vs + 64 * VS_S;                  // 128*68 [row][key]

    const int qt  = blockIdx.x;                  // 0..15
    const int bh  = blockIdx.y;
    const int b   = bh / HH;
    const int h   = bh - b * HH;
    const int kvh = h / GG;
    const int tid = threadIdx.x;
    const int w   = tid >> 5;
    const int l   = tid & 31;
    const int g   = l >> 2;
    const int t4  = l & 3;

    const float* qptr = Q + (((size_t)b * HH + h) * TT + (size_t)qt * 128) * HDIM;
    const float* kptr = K + (((size_t)b * KVH + kvh) * TT) * HDIM;
    const float* vptr = V + (((size_t)b * KVH + kvh) * TT) * HDIM;

    // Load Q tile 128x64 (tf32-rounded)
#pragma unroll
    for (int it = 0; it < 8; it++) {
        int idx = tid + it * 256;     // 0..2047
        int row = idx >> 4;
        int dq  = idx & 15;
        float4 v4 = *(const float4*)&qptr[row * 64 + dq * 4];
        v4.x = to_tf32(v4.x); v4.y = to_tf32(v4.y);
        v4.z = to_tf32(v4.z); v4.w = to_tf32(v4.w);
        *(float4*)&Qs[row * QS_S + dq * 4] = v4;
    }

    const int r0 = qt * 128 + w * 16 + g;   // thread's first global q-row
    const int r1 = r0 + 8;

    float m0 = -1e30f, m1 = -1e30f, l0 = 0.0f, l1 = 0.0f;
    float o[8][4];
#pragma unroll
    for (int nt = 0; nt < 8; nt++)
#pragma unroll
        for (int r = 0; r < 4; r++) o[nt][r] = 0.0f;

    const float scale = 0.125f;
    const int ktmax = 2 * qt + 1;

    for (int kt = 0; kt <= ktmax; kt++) {
        __syncthreads();
        // ---- load K tile transposed: Ks[d][key]  (conflict-free stores) ----
#pragma unroll
        for (int it = 0; it < 2; it++) {
            int idx = tid + it * 256;      // 0..511
            int key = idx & 63;
            int dq  = idx >> 6;            // 0..7 -> d = 8dq..8dq+7 via two float4
#pragma unroll
            for (int half = 0; half < 2; half++) {
                float4 kv = *(const float4*)&kptr[((size_t)kt * 64 + key) * 64 + dq * 8 + half * 4];
                int d0 = dq * 8 + half * 4;
                Ks[(d0 + 0) * KS_S + key] = to_tf32(kv.x);
                Ks[(d0 + 1) * KS_S + key] = to_tf32(kv.y);
                Ks[(d0 + 2) * KS_S + key] = to_tf32(kv.z);
                Ks[(d0 + 3) * KS_S + key] = to_tf32(kv.w);
            }
        }
        // ---- load V tile [key][d] ----
#pragma unroll
        for (int it = 0; it < 4; it++) {
            int idx = tid + it * 256;      // 0..1023
            int row = idx >> 4;
            int dq  = idx & 15;
            float4 v4 = *(const float4*)&vptr[((size_t)kt * 64 + row) * 64 + dq * 4];
            v4.x = to_tf32(v4.x); v4.y = to_tf32(v4.y);
            v4.z = to_tf32(v4.z); v4.w = to_tf32(v4.w);
            *(float4*)&Vs[row * VS_S + dq * 4] = v4;
        }
        __syncthreads();

        // warp fully above the diagonal for this key tile? skip compute
        if (kt * 64 > qt * 128 + w * 16 + 15) continue;

        // ---- S = Q K^T ----
        float s[8][4];
#pragma unroll
        for (int nt = 0; nt < 8; nt++)
#pragma unroll
            for (int r = 0; r < 4; r++) s[nt][r] = 0.0f;

#pragma unroll
        for (int ks = 0; ks < 8; ks++) {
            const int kb = ks * 8;
            uint32_t a0 = __float_as_uint(Qs[(w * 16 + g)     * QS_S + kb + t4]);
            uint32_t a1 = __float_as_uint(Qs[(w * 16 + g + 8) * QS_S + kb + t4]);
            uint32_t a2 = __float_as_uint(Qs[(w * 16 + g)     * QS_S + kb + t4 + 4]);
            uint32_t a3 = __float_as_uint(Qs[(w * 16 + g + 8) * QS_S + kb + t4 + 4]);
#pragma unroll
            for (int nt = 0; nt < 8; nt++) {
                uint32_t b0 = __float_as_uint(Ks[(kb + t4)     * KS_S + nt * 8 + g]);
                uint32_t b1 = __float_as_uint(Ks[(kb + t4 + 4) * KS_S + nt * 8 + g]);
                mma_tf32(s[nt][0], s[nt][1], s[nt][2], s[nt][3], a0, a1, a2, a3, b0, b1);
            }
        }

        // ---- scale + causal mask ----
        if (kt >= 2 * qt) {
            const int kgb = kt * 64 + 2 * t4;
#pragma unroll
            for (int nt = 0; nt < 8; nt++) {
                int kg = kgb + nt * 8;
                s[nt][0] = (kg     > r0) ? -1e30f : s[nt][0] * scale;
                s[nt][1] = (kg + 1 > r0) ? -1e30f : s[nt][1] * scale;
                s[nt][2] = (kg     > r1) ? -1e30f : s[nt][2] * scale;
                s[nt][3] = (kg + 1 > r1) ? -1e30f : s[nt][3] * scale;
            }
        } else {
#pragma unroll
            for (int nt = 0; nt < 8; nt++) {
                s[nt][0] *= scale; s[nt][1] *= scale;
                s[nt][2] *= scale; s[nt][3] *= scale;
            }
        }

        // ---- online softmax (rows r0, r1 per thread; quad reduction) ----
        float rm0 = -1e30f, rm1 = -1e30f;
#pragma unroll
        for (int nt = 0; nt < 8; nt++) {
            rm0 = fmaxf(rm0, fmaxf(s[nt][0], s[nt][1]));
            rm1 = fmaxf(rm1, fmaxf(s[nt][2], s[nt][3]));
        }
        rm0 = fmaxf(rm0, __shfl_xor_sync(0xffffffffu, rm0, 1));
        rm0 = fmaxf(rm0, __shfl_xor_sync(0xffffffffu, rm0, 2));
        rm1 = fmaxf(rm1, __shfl_xor_sync(0xffffffffu, rm1, 1));
        rm1 = fmaxf(rm1, __shfl_xor_sync(0xffffffffu, rm1, 2));

        float nm0 = fmaxf(m0, rm0);
        float nm1 = fmaxf(m1, rm1);
        float al0 = __expf(m0 - nm0);
        float al1 = __expf(m1 - nm1);
        m0 = nm0; m1 = nm1;

        float rs0 = 0.0f, rs1 = 0.0f;
#pragma unroll
        for (int nt = 0; nt < 8; nt++) {
            // exp, round to tf32, accumulate the ROUNDED value (bias cancels)
            float p0 = to_tf32(__expf(s[nt][0] - nm0));
            float p1 = to_tf32(__expf(s[nt][1] - nm0));
            float p2 = to_tf32(__expf(s[nt][2] - nm1));
            float p3 = to_tf32(__expf(s[nt][3] - nm1));
            s[nt][0] = p0; s[nt][1] = p1; s[nt][2] = p2; s[nt][3] = p3;
            rs0 += p0 + p1;
            rs1 += p2 + p3;
        }
        rs0 += __shfl_xor_sync(0xffffffffu, rs0, 1);
        rs0 += __shfl_xor_sync(0xffffffffu, rs0, 2);
        rs1 += __shfl_xor_sync(0xffffffffu, rs1, 1);
        rs1 += __shfl_xor_sync(0xffffffffu, rs1, 2);

        l0 = l0 * al0 + rs0;
        l1 = l1 * al1 + rs1;
#pragma unroll
        for (int nt = 0; nt < 8; nt++) {
            o[nt][0] *= al0; o[nt][1] *= al0;
            o[nt][2] *= al1; o[nt][3] *= al1;
        }

        // ---- store P to smem (warp-private rows) ----
#pragma unroll
        for (int nt = 0; nt < 8; nt++) {
            *(float2*)&Ps[(w * 16 + g)     * PS_S + nt * 8 + 2 * t4] = make_float2(s[nt][0], s[nt][1]);
            *(float2*)&Ps[(w * 16 + g + 8) * PS_S + nt * 8 + 2 * t4] = make_float2(s[nt][2], s[nt][3]);
        }
        __syncwarp();

        // ---- O += P V ----
#pragma unroll
        for (int ks = 0; ks < 8; ks++) {
            const int kb = ks * 8;
            uint32_t a0 = __float_as_uint(Ps[(w * 16 + g)     * PS_S + kb + t4]);
            uint32_t a1 = __float_as_uint(Ps[(w * 16 + g + 8) * PS_S + kb + t4]);
            uint32_t a2 = __float_as_uint(Ps[(w * 16 + g)     * PS_S + kb + t4 + 4]);
            uint32_t a3 = __float_as_uint(Ps[(w * 16 + g + 8) * PS_S + kb + t4 + 4]);
#pragma unroll
            for (int nt = 0; nt < 8; nt++) {
                uint32_t b0 = __float_as_uint(Vs[(kb + t4)     * VS_S + nt * 8 + g]);
                uint32_t b1 = __float_as_uint(Vs[(kb + t4 + 4) * VS_S + nt * 8 + g]);
                mma_tf32(o[nt][0], o[nt][1], o[nt][2], o[nt][3], a0, a1, a2, a3, b0, b1);
            }
        }
    }

    // ---- finalize + write [b*T + t][h*64 + d] ----
    float inv0 = 1.0f / l0;
    float inv1 = 1.0f / l1;
    size_t row0 = (size_t)b * TT + (size_t)qt * 128 + w * 16 + g;
#pragma unroll
    for (int nt = 0; nt < 8; nt++) {
        int col = h * HDIM + nt * 8 + 2 * t4;
        *(float2*)&Ob[row0 * DD + col]       = make_float2(o[nt][0] * inv0, o[nt][1] * inv0);
        *(float2*)&Ob[(row0 + 8) * DD + col] = make_float2(o[nt][2] * inv1, o[nt][3] * inv1);
    }
}

// ---------------------------------------------------------------------------
extern "C" void kernel_launch(void* const* d_in, const int* in_sizes, int n_in,
                              void* d_out, int out_size)
{
    const float* x    = (const float*)d_in[0];
    const float* Wqkv = (const float*)d_in[1];
    const float* Wout = (const float*)d_in[2];
    const float* bout = (const float*)d_in[3];
    const float* rcos = (const float*)d_in[4];
    const float* rsin = (const float*)d_in[5];
    float* out = (float*)d_out;

    float *qkv, *q, *k, *v, *attn;
    cudaGetSymbolAddress((void**)&qkv,  g_qkv);
    cudaGetSymbolAddress((void**)&q,    g_q);
    cudaGetSymbolAddress((void**)&k,    g_k);
    cudaGetSymbolAddress((void**)&v,    g_v);
    cudaGetSymbolAddress((void**)&attn, g_attn);

    // 1. QKV projection (tf32 tensor cores)
    {
        dim3 grid(NQKV / 128, MM / 128);
        mma_gemm_kernel<0><<<grid, 256>>>(x, Wqkv, qkv, nullptr, MM, NQKV, DD);
    }

    // 2. RoPE + split
    {
        int tot = MM * (NQKV / 2);
        rope_split_kernel<<<(tot + 255) / 256, 256>>>(qkv, rcos, rsin, q, k, v);
    }

    // 3. Causal flash attention (tf32 tensor cores)
    {
        int smem = (128 * QS_S + 64 * KS_S + 64 * VS_S + 128 * PS_S) * sizeof(float); // 106496
        cudaFuncSetAttribute(flash_kernel, cudaFuncAttributeMaxDynamicSharedMemorySize, smem);
        dim3 grid(TT / 128, BB * HH);
        flash_kernel<<<grid, 256, smem>>>(q, k, v, attn);
    }

    // 4. Out projection + bias + nan_to_num (tf32 tensor cores)
    {
        dim3 grid(DD / 128, MM / 128);
        mma_gemm_kernel<1><<<grid, 256>>>(attn, Wout, out, bout, MM, DD, DD);
    }
}

// round 6
// speedup vs baseline: 3.5012x; 1.0560x over previous
#include <cuda_runtime.h>
#include <cuda_bf16.h>
#include <math.h>
#include <stdint.h>

// Problem constants
#define BB 2
#define TT 2048
#define DD 2048
#define HH 32
#define KVH 8
#define HDIM 64
#define GG 4
#define NQKV 3072
#define MM (BB*TT)

// ---------------- scratch ----------
__device__ float g_qkv[MM * NQKV];
__device__ float g_q[(size_t)BB * HH * TT * HDIM];
__device__ float g_k[(size_t)BB * KVH * TT * HDIM];
__device__ float g_v[(size_t)BB * KVH * TT * HDIM];
__device__ float g_attn[(size_t)MM * DD];
__device__ float g_x32[(size_t)MM * DD];        // tf32-rounded x
__device__ float g_wqkv32[(size_t)DD * NQKV];   // tf32-rounded W_qkv
__device__ float g_wout32[(size_t)DD * DD];     // tf32-rounded W_out

__device__ __forceinline__ float nan_clamp(float x) {
    if (isnan(x)) return 0.0f;
    if (isinf(x)) return x > 0.0f ? 10000.0f : -10000.0f;
    return x;
}

__device__ __forceinline__ float to_tf32(float x) {
    uint32_t u;
    asm("cvt.rna.tf32.f32 %0, %1;" : "=r"(u) : "f"(x));
    return __uint_as_float(u);
}

__device__ __forceinline__ void mma_tf32(float& c0, float& c1, float& c2, float& c3,
                                         uint32_t a0, uint32_t a1, uint32_t a2, uint32_t a3,
                                         uint32_t b0, uint32_t b1) {
    asm volatile(
        "mma.sync.aligned.m16n8k8.row.col.f32.tf32.tf32.f32 "
        "{%0,%1,%2,%3}, {%4,%5,%6,%7}, {%8,%9}, {%0,%1,%2,%3};\n"
        : "+f"(c0), "+f"(c1), "+f"(c2), "+f"(c3)
        : "r"(a0), "r"(a1), "r"(a2), "r"(a3), "r"(b0), "r"(b1));
}

__device__ __forceinline__ void cp_async16(void* smem_dst, const void* gmem_src) {
    uint32_t dst = (uint32_t)__cvta_generic_to_shared(smem_dst);
    asm volatile("cp.async.cg.shared.global [%0], [%1], 16;\n" :: "r"(dst), "l"(gmem_src));
}

// ---------------------------------------------------------------------------
// Elementwise tf32 rounding pass (float4 grid-stride)
// ---------------------------------------------------------------------------
__global__ void round_tf32_kernel(const float* __restrict__ in, float* __restrict__ out, int n4)
{
    int stride = gridDim.x * blockDim.x;
    for (int i = blockIdx.x * blockDim.x + threadIdx.x; i < n4; i += stride) {
        float4 v = ((const float4*)in)[i];
        v.x = to_tf32(v.x); v.y = to_tf32(v.y);
        v.z = to_tf32(v.z); v.w = to_tf32(v.w);
        ((float4*)out)[i] = v;
    }
}

// ---------------------------------------------------------------------------
// TF32 tensor-core GEMM, 3-stage cp.async pipeline.
// Inputs MUST be pre-rounded to tf32 (raw 16B async copies).
// 128x128 CTA tile, BK=32, 8 warps (2x4), 64x32 warp tile.
// ---------------------------------------------------------------------------
#define AS_S 36
#define BS_S 136
#define STAGE_F (128 * AS_S + 32 * BS_S)   // 8960 floats = 35840 B per stage

template <int EPI>
__global__ void __launch_bounds__(256, 2) mma_gemm_kernel(
    const float* __restrict__ A, const float* __restrict__ Bm,
    float* __restrict__ C, const float* __restrict__ bias,
    int Md, int Nd, int Kd)
{
    extern __shared__ float smem[];

    const int tid = threadIdx.x;
    const int m0 = blockIdx.y * 128;
    const int n0 = blockIdx.x * 128;

    const int w  = tid >> 5;
    const int l  = tid & 31;
    const int wm = (w >> 2) * 64;
    const int wn = (w & 3) * 32;
    const int g  = l >> 2;
    const int t4 = l & 3;

    // per-thread load coordinates (fixed)
    const int am = tid >> 1;                 // A: rows tid/2, two iterations cover 128 rows? no:
    // A tile: 128x32 = 1024 float4; thread does 4 (idx = tid + it*256): m=idx>>3, kq=idx&7
    // B tile: 32x128 = 1024 float4; kb=idx>>5, nq=idx&31

    float acc[4][4][4];
#pragma unroll
    for (int mt = 0; mt < 4; mt++)
#pragma unroll
        for (int nt = 0; nt < 4; nt++)
#pragma unroll
            for (int r = 0; r < 4; r++) acc[mt][nt][r] = 0.0f;

    const int nk = Kd >> 5;

    // ---- stage issue helper (macro-ish lambda) ----
    auto issue_stage = [&](int k0, int s) {
        float* As = smem + s * STAGE_F;
        float* Bs = As + 128 * AS_S;
#pragma unroll
        for (int it = 0; it < 4; it++) {
            int idx = tid + it * 256;
            int m   = idx >> 3;
            int kq  = idx & 7;
            cp_async16(&As[m * AS_S + kq * 4], &A[(size_t)(m0 + m) * Kd + k0 + kq * 4]);
        }
#pragma unroll
        for (int it = 0; it < 4; it++) {
            int idx = tid + it * 256;
            int kb  = idx >> 5;
            int nq  = idx & 31;
            cp_async16(&Bs[kb * BS_S + nq * 4], &Bm[(size_t)(k0 + kb) * Nd + n0 + nq * 4]);
        }
        asm volatile("cp.async.commit_group;\n");
    };

    issue_stage(0, 0);
    issue_stage(32, 1);

    for (int k = 0; k < nk; k++) {
        asm volatile("cp.async.wait_group 1;\n");
        __syncthreads();

        // refill the buffer computed last iteration (safe: all warps passed the barrier)
        if (k + 2 < nk) issue_stage((k + 2) << 5, (k + 2) % 3);

        const float* As = smem + (k % 3) * STAGE_F;
        const float* Bs = As + 128 * AS_S;

#pragma unroll
        for (int ks = 0; ks < 4; ks++) {
            const int kb = ks * 8;
            uint32_t af[4][4], bf[4][2];
#pragma unroll
            for (int mt = 0; mt < 4; mt++) {
                int bm = wm + mt * 16;
                af[mt][0] = __float_as_uint(As[(bm + g)     * AS_S + kb + t4]);
                af[mt][1] = __float_as_uint(As[(bm + g + 8) * AS_S + kb + t4]);
                af[mt][2] = __float_as_uint(As[(bm + g)     * AS_S + kb + t4 + 4]);
                af[mt][3] = __float_as_uint(As[(bm + g + 8) * AS_S + kb + t4 + 4]);
            }
#pragma unroll
            for (int nt = 0; nt < 4; nt++) {
                int bn = wn + nt * 8;
                bf[nt][0] = __float_as_uint(Bs[(kb + t4)     * BS_S + bn + g]);
                bf[nt][1] = __float_as_uint(Bs[(kb + t4 + 4) * BS_S + bn + g]);
            }
#pragma unroll
            for (int mt = 0; mt < 4; mt++)
#pragma unroll
                for (int nt = 0; nt < 4; nt++)
                    mma_tf32(acc[mt][nt][0], acc[mt][nt][1], acc[mt][nt][2], acc[mt][nt][3],
                             af[mt][0], af[mt][1], af[mt][2], af[mt][3],
                             bf[nt][0], bf[nt][1]);
        }
    }

#pragma unroll
    for (int mt = 0; mt < 4; mt++) {
#pragma unroll
        for (int nt = 0; nt < 4; nt++) {
            int row = m0 + wm + mt * 16 + g;
            int col = n0 + wn + nt * 8 + 2 * t4;
            float2 v0 = make_float2(acc[mt][nt][0], acc[mt][nt][1]);
            float2 v1 = make_float2(acc[mt][nt][2], acc[mt][nt][3]);
            if (EPI) {
                v0.x = nan_clamp(v0.x + bias[col]);
                v0.y = nan_clamp(v0.y + bias[col + 1]);
                v1.x = nan_clamp(v1.x + bias[col]);
                v1.y = nan_clamp(v1.y + bias[col + 1]);
            }
            *(float2*)&C[(size_t)row * Nd + col]       = v0;
            *(float2*)&C[(size_t)(row + 8) * Nd + col] = v1;
        }
    }
}

// ---------------------------------------------------------------------------
// RoPE + split (unchanged)
// ---------------------------------------------------------------------------
__global__ void rope_split_kernel(
    const float* __restrict__ qkv,
    const float* __restrict__ rcos, const float* __restrict__ rsin,
    float* __restrict__ q, float* __restrict__ k, float* __restrict__ v)
{
    int idx = blockIdx.x * blockDim.x + threadIdx.x;
    const int TOT = MM * (NQKV / 2);
    if (idx >= TOT) return;
    int m  = idx / (NQKV / 2);
    int c2 = idx - m * (NQKV / 2);
    int c  = c2 * 2;
    int b = m >> 11;
    int t = m & (TT - 1);

    float e = qkv[(size_t)m * NQKV + c];
    float o = qkv[(size_t)m * NQKV + c + 1];
    int d = c & (HDIM - 1);
    int i = d >> 1;

    if (c < HH * HDIM) {
        int h = c >> 6;
        float cs = rcos[t * (HDIM / 2) + i];
        float sn = rsin[t * (HDIM / 2) + i];
        size_t base = (((size_t)b * HH + h) * TT + t) * HDIM + d;
        q[base]     = e * cs - o * sn;
        q[base + 1] = e * sn + o * cs;
    } else if (c < HH * HDIM + KVH * HDIM) {
        int kh = (c - HH * HDIM) >> 6;
        float cs = rcos[t * (HDIM / 2) + i];
        float sn = rsin[t * (HDIM / 2) + i];
        size_t base = (((size_t)b * KVH + kh) * TT + t) * HDIM + d;
        k[base]     = e * cs - o * sn;
        k[base + 1] = e * sn + o * cs;
    } else {
        int kh = (c - HH * HDIM - KVH * HDIM) >> 6;
        size_t base = (((size_t)b * KVH + kh) * TT + t) * HDIM + d;
        v[base]     = e;
        v[base + 1] = o;
    }
}

// ---------------------------------------------------------------------------
// Causal flash attention on tf32 tensor cores (epilogue now tf32-rounds O
// so the out-projection can raw-copy its A operand).
// ---------------------------------------------------------------------------
#define QS_S 68
#define KS_S 72
#define VS_S 72
#define PS_S 68

__global__ void __launch_bounds__(256) flash_kernel(
    const float* __restrict__ Q, const float* __restrict__ K,
    const float* __restrict__ V, float* __restrict__ Ob)
{
    extern __shared__ float sm[];
    float* Qs = sm;
    float* Ks = Qs + 128 * QS_S;
    float* Vs = Ks + 64 * KS_S;
    float* Ps = Vs + 64 * VS_S;

    const int qt  = blockIdx.x;
    const int bh  = blockIdx.y;
    const int b   = bh / HH;
    const int h   = bh - b * HH;
    const int kvh = h / GG;
    const int tid = threadIdx.x;
    const int w   = tid >> 5;
    const int l   = tid & 31;
    const int g   = l >> 2;
    const int t4  = l & 3;

    const float* qptr = Q + (((size_t)b * HH + h) * TT + (size_t)qt * 128) * HDIM;
    const float* kptr = K + (((size_t)b * KVH + kvh) * TT) * HDIM;
    const float* vptr = V + (((size_t)b * KVH + kvh) * TT) * HDIM;

#pragma unroll
    for (int it = 0; it < 8; it++) {
        int idx = tid + it * 256;
        int row = idx >> 4;
        int dq  = idx & 15;
        float4 v4 = *(const float4*)&qptr[row * 64 + dq * 4];
        v4.x = to_tf32(v4.x); v4.y = to_tf32(v4.y);
        v4.z = to_tf32(v4.z); v4.w = to_tf32(v4.w);
        *(float4*)&Qs[row * QS_S + dq * 4] = v4;
    }

    const int r0 = qt * 128 + w * 16 + g;
    const int r1 = r0 + 8;

    float m0 = -1e30f, m1 = -1e30f, l0 = 0.0f, l1 = 0.0f;
    float o[8][4];
#pragma unroll
    for (int nt = 0; nt < 8; nt++)
#pragma unroll
        for (int r = 0; r < 4; r++) o[nt][r] = 0.0f;

    const float scale = 0.125f;
    const int ktmax = 2 * qt + 1;

    for (int kt = 0; kt <= ktmax; kt++) {
        __syncthreads();
#pragma unroll
        for (int it = 0; it < 2; it++) {
            int idx = tid + it * 256;
            int key = idx & 63;
            int dq  = idx >> 6;
#pragma unroll
            for (int half = 0; half < 2; half++) {
                float4 kv = *(const float4*)&kptr[((size_t)kt * 64 + key) * 64 + dq * 8 + half * 4];
                int d0 = dq * 8 + half * 4;
                Ks[(d0 + 0) * KS_S + key] = to_tf32(kv.x);
                Ks[(d0 + 1) * KS_S + key] = to_tf32(kv.y);
                Ks[(d0 + 2) * KS_S + key] = to_tf32(kv.z);
                Ks[(d0 + 3) * KS_S + key] = to_tf32(kv.w);
            }
        }
#pragma unroll
        for (int it = 0; it < 4; it++) {
            int idx = tid + it * 256;
            int row = idx >> 4;
            int dq  = idx & 15;
            float4 v4 = *(const float4*)&vptr[((size_t)kt * 64 + row) * 64 + dq * 4];
            v4.x = to_tf32(v4.x); v4.y = to_tf32(v4.y);
            v4.z = to_tf32(v4.z); v4.w = to_tf32(v4.w);
            *(float4*)&Vs[row * VS_S + dq * 4] = v4;
        }
        __syncthreads();

        if (kt * 64 > qt * 128 + w * 16 + 15) continue;

        float s[8][4];
#pragma unroll
        for (int nt = 0; nt < 8; nt++)
#pragma unroll
            for (int r = 0; r < 4; r++) s[nt][r] = 0.0f;

#pragma unroll
        for (int ks = 0; ks < 8; ks++) {
            const int kb = ks * 8;
            uint32_t a0 = __float_as_uint(Qs[(w * 16 + g)     * QS_S + kb + t4]);
            uint32_t a1 = __float_as_uint(Qs[(w * 16 + g + 8) * QS_S + kb + t4]);
            uint32_t a2 = __float_as_uint(Qs[(w * 16 + g)     * QS_S + kb + t4 + 4]);
            uint32_t a3 = __float_as_uint(Qs[(w * 16 + g + 8) * QS_S + kb + t4 + 4]);
#pragma unroll
            for (int nt = 0; nt < 8; nt++) {
                uint32_t b0 = __float_as_uint(Ks[(kb + t4)     * KS_S + nt * 8 + g]);
                uint32_t b1 = __float_as_uint(Ks[(kb + t4 + 4) * KS_S + nt * 8 + g]);
                mma_tf32(s[nt][0], s[nt][1], s[nt][2], s[nt][3], a0, a1, a2, a3, b0, b1);
            }
        }

        if (kt >= 2 * qt) {
            const int kgb = kt * 64 + 2 * t4;
#pragma unroll
            for (int nt = 0; nt < 8; nt++) {
                int kg = kgb + nt * 8;
                s[nt][0] = (kg     > r0) ? -1e30f : s[nt][0] * scale;
                s[nt][1] = (kg + 1 > r0) ? -1e30f : s[nt][1] * scale;
                s[nt][2] = (kg     > r1) ? -1e30f : s[nt][2] * scale;
                s[nt][3] = (kg + 1 > r1) ? -1e30f : s[nt][3] * scale;
            }
        } else {
#pragma unroll
            for (int nt = 0; nt < 8; nt++) {
                s[nt][0] *= scale; s[nt][1] *= scale;
                s[nt][2] *= scale; s[nt][3] *= scale;
            }
        }

        float rm0 = -1e30f, rm1 = -1e30f;
#pragma unroll
        for (int nt = 0; nt < 8; nt++) {
            rm0 = fmaxf(rm0, fmaxf(s[nt][0], s[nt][1]));
            rm1 = fmaxf(rm1, fmaxf(s[nt][2], s[nt][3]));
        }
        rm0 = fmaxf(rm0, __shfl_xor_sync(0xffffffffu, rm0, 1));
        rm0 = fmaxf(rm0, __shfl_xor_sync(0xffffffffu, rm0, 2));
        rm1 = fmaxf(rm1, __shfl_xor_sync(0xffffffffu, rm1, 1));
        rm1 = fmaxf(rm1, __shfl_xor_sync(0xffffffffu, rm1, 2));

        float nm0 = fmaxf(m0, rm0);
        float nm1 = fmaxf(m1, rm1);
        float al0 = __expf(m0 - nm0);
        float al1 = __expf(m1 - nm1);
        m0 = nm0; m1 = nm1;

        float rs0 = 0.0f, rs1 = 0.0f;
#pragma unroll
        for (int nt = 0; nt < 8; nt++) {
            float p0 = to_tf32(__expf(s[nt][0] - nm0));
            float p1 = to_tf32(__expf(s[nt][1] - nm0));
            float p2 = to_tf32(__expf(s[nt][2] - nm1));
            float p3 = to_tf32(__expf(s[nt][3] - nm1));
            s[nt][0] = p0; s[nt][1] = p1; s[nt][2] = p2; s[nt][3] = p3;
            rs0 += p0 + p1;
            rs1 += p2 + p3;
        }
        rs0 += __shfl_xor_sync(0xffffffffu, rs0, 1);
        rs0 += __shfl_xor_sync(0xffffffffu, rs0, 2);
        rs1 += __shfl_xor_sync(0xffffffffu, rs1, 1);
        rs1 += __shfl_xor_sync(0xffffffffu, rs1, 2);

        l0 = l0 * al0 + rs0;
        l1 = l1 * al1 + rs1;
#pragma unroll
        for (int nt = 0; nt < 8; nt++) {
            o[nt][0] *= al0; o[nt][1] *= al0;
            o[nt][2] *= al1; o[nt][3] *= al1;
        }

#pragma unroll
        for (int nt = 0; nt < 8; nt++) {
            *(float2*)&Ps[(w * 16 + g)     * PS_S + nt * 8 + 2 * t4] = make_float2(s[nt][0], s[nt][1]);
            *(float2*)&Ps[(w * 16 + g + 8) * PS_S + nt * 8 + 2 * t4] = make_float2(s[nt][2], s[nt][3]);
        }
        __syncwarp();

#pragma unroll
        for (int ks = 0; ks < 8; ks++) {
            const int kb = ks * 8;
            uint32_t a0 = __float_as_uint(Ps[(w * 16 + g)     * PS_S + kb + t4]);
            uint32_t a1 = __float_as_uint(Ps[(w * 16 + g + 8) * PS_S + kb + t4]);
            uint32_t a2 = __float_as_uint(Ps[(w * 16 + g)     * PS_S + kb + t4 + 4]);
            uint32_t a3 = __float_as_uint(Ps[(w * 16 + g + 8) * PS_S + kb + t4 + 4]);
#pragma unroll
            for (int nt = 0; nt < 8; nt++) {
                uint32_t b0 = __float_as_uint(Vs[(kb + t4)     * VS_S + nt * 8 + g]);
                uint32_t b1 = __float_as_uint(Vs[(kb + t4 + 4) * VS_S + nt * 8 + g]);
                mma_tf32(o[nt][0], o[nt][1], o[nt][2], o[nt][3], a0, a1, a2, a3, b0, b1);
            }
        }
    }

    // finalize + tf32-round O (feeds raw-copy out-projection)
    float inv0 = 1.0f / l0;
    float inv1 = 1.0f / l1;
    size_t row0 = (size_t)b * TT + (size_t)qt * 128 + w * 16 + g;
#pragma unroll
    for (int nt = 0; nt < 8; nt++) {
        int col = h * HDIM + nt * 8 + 2 * t4;
        *(float2*)&Ob[row0 * DD + col] =
            make_float2(to_tf32(o[nt][0] * inv0), to_tf32(o[nt][1] * inv0));
        *(float2*)&Ob[(row0 + 8) * DD + col] =
            make_float2(to_tf32(o[nt][2] * inv1), to_tf32(o[nt][3] * inv1));
    }
}

// ---------------------------------------------------------------------------
extern "C" void kernel_launch(void* const* d_in, const int* in_sizes, int n_in,
                              void* d_out, int out_size)
{
    const float* x    = (const float*)d_in[0];
    const float* Wqkv = (const float*)d_in[1];
    const float* Wout = (const float*)d_in[2];
    const float* bout = (const float*)d_in[3];
    const float* rcos = (const float*)d_in[4];
    const float* rsin = (const float*)d_in[5];
    float* out = (float*)d_out;

    float *qkv, *q, *k, *v, *attn, *x32, *wqkv32, *wout32;
    cudaGetSymbolAddress((void**)&qkv,    g_qkv);
    cudaGetSymbolAddress((void**)&q,      g_q);
    cudaGetSymbolAddress((void**)&k,      g_k);
    cudaGetSymbolAddress((void**)&v,      g_v);
    cudaGetSymbolAddress((void**)&attn,   g_attn);
    cudaGetSymbolAddress((void**)&x32,    g_x32);
    cudaGetSymbolAddress((void**)&wqkv32, g_wqkv32);
    cudaGetSymbolAddress((void**)&wout32, g_wout32);

    // 0. Pre-round GEMM operands to tf32 (enables raw cp.async in GEMMs)
    round_tf32_kernel<<<1184, 256>>>(x,    x32,    (MM * DD) / 4);
    round_tf32_kernel<<<1184, 256>>>(Wqkv, wqkv32, (DD * NQKV) / 4);
    round_tf32_kernel<<<1184, 256>>>(Wout, wout32, (DD * DD) / 4);

    const int gemm_smem = 3 * STAGE_F * sizeof(float);   // 107520 B

    // 1. QKV projection (tf32, pipelined)
    {
        cudaFuncSetAttribute(mma_gemm_kernel<0>, cudaFuncAttributeMaxDynamicSharedMemorySize, gemm_smem);
        dim3 grid(NQKV / 128, MM / 128);
        mma_gemm_kernel<0><<<grid, 256, gemm_smem>>>(x32, wqkv32, qkv, nullptr, MM, NQKV, DD);
    }

    // 2. RoPE + split
    {
        int tot = MM * (NQKV / 2);
        rope_split_kernel<<<(tot + 255) / 256, 256>>>(qkv, rcos, rsin, q, k, v);
    }

    // 3. Causal flash attention (tf32 tensor cores)
    {
        int smem = (128 * QS_S + 64 * KS_S + 64 * VS_S + 128 * PS_S) * sizeof(float);
        cudaFuncSetAttribute(flash_kernel, cudaFuncAttributeMaxDynamicSharedMemorySize, smem);
        dim3 grid(TT / 128, BB * HH);
        flash_kernel<<<grid, 256, smem>>>(q, k, v, attn);
    }

    // 4. Out projection + bias + nan_to_num (tf32, pipelined)
    {
        cudaFuncSetAttribute(mma_gemm_kernel<1>, cudaFuncAttributeMaxDynamicSharedMemorySize, gemm_smem);
        dim3 grid(DD / 128, MM / 128);
        mma_gemm_kernel<1><<<grid, 256, gemm_smem>>>(attn, wout32, out, bout, MM, DD, DD);
    }
}

// round 11
// speedup vs baseline: 3.6433x; 1.0406x over previous
#include <cuda_runtime.h>
#include <cuda_bf16.h>
#include <math.h>
#include <stdint.h>

// Problem constants
#define BB 2
#define TT 2048
#define DD 2048
#define HH 32
#define KVH 8
#define HDIM 64
#define GG 4
#define NQKV 3072
#define MM (BB*TT)

// ---------------- scratch ----------
__device__ float g_qkv[MM * NQKV];
__device__ float g_q[(size_t)BB * HH * TT * HDIM];
__device__ float g_k[(size_t)BB * KVH * TT * HDIM];
__device__ float g_v[(size_t)BB * KVH * TT * HDIM];
__device__ float g_attn[(size_t)MM * DD];
__device__ float g_x32[(size_t)MM * DD];         // tf32-rounded x
__device__ float g_wqkvT[(size_t)NQKV * DD];     // tf32-rounded W_qkv^T  [N][K]
__device__ float g_woutT[(size_t)DD * DD];       // tf32-rounded W_out^T  [N][K]

__device__ __forceinline__ float nan_clamp(float x) {
    if (isnan(x)) return 0.0f;
    if (isinf(x)) return x > 0.0f ? 10000.0f : -10000.0f;
    return x;
}

__device__ __forceinline__ float to_tf32(float x) {
    uint32_t u;
    asm("cvt.rna.tf32.f32 %0, %1;" : "=r"(u) : "f"(x));
    return __uint_as_float(u);
}

__device__ __forceinline__ void mma_tf32(float& c0, float& c1, float& c2, float& c3,
                                         uint32_t a0, uint32_t a1, uint32_t a2, uint32_t a3,
                                         uint32_t b0, uint32_t b1) {
    asm volatile(
        "mma.sync.aligned.m16n8k8.row.col.f32.tf32.tf32.f32 "
        "{%0,%1,%2,%3}, {%4,%5,%6,%7}, {%8,%9}, {%0,%1,%2,%3};\n"
        : "+f"(c0), "+f"(c1), "+f"(c2), "+f"(c3)
        : "r"(a0), "r"(a1), "r"(a2), "r"(a3), "r"(b0), "r"(b1));
}

__device__ __forceinline__ void ldsm_x4(uint32_t& r0, uint32_t& r1, uint32_t& r2, uint32_t& r3,
                                        uint32_t saddr) {
    asm volatile("ldmatrix.sync.aligned.m8n8.x4.shared.b16 {%0,%1,%2,%3}, [%4];\n"
                 : "=r"(r0), "=r"(r1), "=r"(r2), "=r"(r3) : "r"(saddr) : "memory");
}

__device__ __forceinline__ void cp_async16(void* smem_dst, const void* gmem_src) {
    uint32_t dst = (uint32_t)__cvta_generic_to_shared(smem_dst);
    asm volatile("cp.async.cg.shared.global [%0], [%1], 16;\n" :: "r"(dst), "l"(gmem_src));
}

// ---------------------------------------------------------------------------
// Prep: elementwise tf32 round (x) and round+transpose (weights -> [N][K])
// ---------------------------------------------------------------------------
__global__ void round_tf32_kernel(const float* __restrict__ in, float* __restrict__ out, int n4)
{
    int stride = gridDim.x * blockDim.x;
    for (int i = blockIdx.x * blockDim.x + threadIdx.x; i < n4; i += stride) {
        float4 v = ((const float4*)in)[i];
        v.x = to_tf32(v.x); v.y = to_tf32(v.y);
        v.z = to_tf32(v.z); v.w = to_tf32(v.w);
        ((float4*)out)[i] = v;
    }
}

// in: [K][N] row-major -> out: [N][K] row-major, tf32-rounded
__global__ void transpose_round_kernel(const float* __restrict__ in, float* __restrict__ out,
                                       int K, int N)
{
    __shared__ float tile[32][33];
    int k0 = blockIdx.y * 32;
    int n0 = blockIdx.x * 32;
    int tx = threadIdx.x;
    int ty = threadIdx.y;
#pragma unroll
    for (int j = 0; j < 4; j++) {
        int kk = ty + j * 8;
        tile[kk][tx] = to_tf32(in[(size_t)(k0 + kk) * N + n0 + tx]);
    }
    __syncthreads();
#pragma unroll
    for (int j = 0; j < 4; j++) {
        int nn = ty + j * 8;
        out[(size_t)(n0 + nn) * K + k0 + tx] = tile[tx][nn];
    }
}

// ---------------------------------------------------------------------------
// TF32 GEMM: C[M,N] = A[M,K] @ W^T  (W supplied transposed: Bt[N][K]).
// 128x128 CTA tile, BK=32, 3-stage cp.async ring, ldmatrix fragment loads.
// As: [m][k] stride 36, Bs: [n][k] stride 36.
// ---------------------------------------------------------------------------
#define TS 36
#define STAGE_F (2 * 128 * TS)    // 9216 floats = 36864 B per stage

template <int EPI>
__global__ void __launch_bounds__(256, 2) mma_gemm_kernel(
    const float* __restrict__ A, const float* __restrict__ Bt,
    float* __restrict__ C, const float* __restrict__ bias,
    int Md, int Nd, int Kd)
{
    extern __shared__ float smem[];

    const int tid = threadIdx.x;
    const int m0 = blockIdx.y * 128;
    const int n0 = blockIdx.x * 128;

    const int w  = tid >> 5;
    const int l  = tid & 31;
    const int wm = (w >> 2) * 64;
    const int wn = (w & 3) * 32;
    const int g  = l >> 2;
    const int t4 = l & 3;

    const uint32_t smem_u32 = (uint32_t)__cvta_generic_to_shared(smem);
    const int a_row = ((l >> 3) & 1) * 8 + (l & 7);
    const int a_k   = (l >> 4) * 4;
    const uint32_t a_base = (uint32_t)(((wm + a_row) * TS + a_k) * 4);
    const int b_row = l & 7;
    const int b_k   = (l >> 3) * 4;
    const uint32_t b_base = (uint32_t)((128 * TS + (wn + b_row) * TS + b_k) * 4);

    float acc[4][4][4];
#pragma unroll
    for (int mt = 0; mt < 4; mt++)
#pragma unroll
        for (int nt = 0; nt < 4; nt++)
#pragma unroll
            for (int r = 0; r < 4; r++) acc[mt][nt][r] = 0.0f;

    const int nk = Kd >> 5;

    auto issue_stage = [&](int k0, int s) {
        float* As = smem + s * STAGE_F;
        float* Bs = As + 128 * TS;
#pragma unroll
        for (int it = 0; it < 4; it++) {
            int idx = tid + it * 256;
            int m   = idx >> 3;
            int kq  = idx & 7;
            cp_async16(&As[m * TS + kq * 4], &A[(size_t)(m0 + m) * Kd + k0 + kq * 4]);
        }
#pragma unroll
        for (int it = 0; it < 4; it++) {
            int idx = tid + it * 256;
            int n   = idx >> 3;
            int kq  = idx & 7;
            cp_async16(&Bs[n * TS + kq * 4], &Bt[(size_t)(n0 + n) * Kd + k0 + kq * 4]);
        }
        asm volatile("cp.async.commit_group;\n");
    };

    issue_stage(0, 0);
    issue_stage(32, 1);

    for (int k = 0; k < nk; k++) {
        asm volatile("cp.async.wait_group 1;\n" ::: "memory");
        __syncthreads();

        if (k + 2 < nk) issue_stage((k + 2) << 5, (k + 2) % 3);

        const uint32_t stage = smem_u32 + (uint32_t)((k % 3) * STAGE_F * 4);
        const uint32_t a_addr = stage + a_base;
        const uint32_t b_addr = stage + b_base;

#pragma unroll
        for (int kp = 0; kp < 2; kp++) {      // BK=32: kp*16 covers k 0..31
            uint32_t bf[4][4];
#pragma unroll
            for (int nt = 0; nt < 4; nt++)
                ldsm_x4(bf[nt][0], bf[nt][1], bf[nt][2], bf[nt][3],
                        b_addr + (uint32_t)((nt * 8 * TS + kp * 16) * 4));
#pragma unroll
            for (int h = 0; h < 2; h++) {
                const int kb = kp * 16 + h * 8;
                uint32_t af[4][4];
#pragma unroll
                for (int mt = 0; mt < 4; mt++)
                    ldsm_x4(af[mt][0], af[mt][1], af[mt][2], af[mt][3],
                            a_addr + (uint32_t)((mt * 16 * TS + kb) * 4));
#pragma unroll
                for (int mt = 0; mt < 4; mt++)
#pragma unroll
                    for (int nt = 0; nt < 4; nt++)
                        mma_tf32(acc[mt][nt][0], acc[mt][nt][1], acc[mt][nt][2], acc[mt][nt][3],
                                 af[mt][0], af[mt][1], af[mt][2], af[mt][3],
                                 bf[nt][2 * h], bf[nt][2 * h + 1]);
            }
        }
    }

#pragma unroll
    for (int mt = 0; mt < 4; mt++) {
#pragma unroll
        for (int nt = 0; nt < 4; nt++) {
            int row = m0 + wm + mt * 16 + g;
            int col = n0 + wn + nt * 8 + 2 * t4;
            float2 v0 = make_float2(acc[mt][nt][0], acc[mt][nt][1]);
            float2 v1 = make_float2(acc[mt][nt][2], acc[mt][nt][3]);
            if (EPI) {
                v0.x = nan_clamp(v0.x + bias[col]);
                v0.y = nan_clamp(v0.y + bias[col + 1]);
                v1.x = nan_clamp(v1.x + bias[col]);
                v1.y = nan_clamp(v1.y + bias[col + 1]);
            }
            *(float2*)&C[(size_t)row * Nd + col]       = v0;
            *(float2*)&C[(size_t)(row + 8) * Nd + col] = v1;
        }
    }
}

// ---------------------------------------------------------------------------
// RoPE + split; outputs tf32-rounded q/k/v (flash does raw loads).
// ---------------------------------------------------------------------------
__global__ void rope_split_kernel(
    const float* __restrict__ qkv,
    const float* __restrict__ rcos, const float* __restrict__ rsin,
    float* __restrict__ q, float* __restrict__ k, float* __restrict__ v)
{
    int idx = blockIdx.x * blockDim.x + threadIdx.x;
    const int TOT = MM * (NQKV / 2);
    if (idx >= TOT) return;
    int m  = idx / (NQKV / 2);
    int c2 = idx - m * (NQKV / 2);
    int c  = c2 * 2;
    int b = m >> 11;
    int t = m & (TT - 1);

    float e = qkv[(size_t)m * NQKV + c];
    float o = qkv[(size_t)m * NQKV + c + 1];
    int d = c & (HDIM - 1);
    int i = d >> 1;

    if (c < HH * HDIM) {
        int h = c >> 6;
        float cs = rcos[t * (HDIM / 2) + i];
        float sn = rsin[t * (HDIM / 2) + i];
        size_t base = (((size_t)b * HH + h) * TT + t) * HDIM + d;
        q[base]     = to_tf32(e * cs - o * sn);
        q[base + 1] = to_tf32(e * sn + o * cs);
    } else if (c < HH * HDIM + KVH * HDIM) {
        int kh = (c - HH * HDIM) >> 6;
        float cs = rcos[t * (HDIM / 2) + i];
        float sn = rsin[t * (HDIM / 2) + i];
        size_t base = (((size_t)b * KVH + kh) * TT + t) * HDIM + d;
        k[base]     = to_tf32(e * cs - o * sn);
        k[base + 1] = to_tf32(e * sn + o * cs);
    } else {
        int kh = (c - HH * HDIM - KVH * HDIM) >> 6;
        size_t base = (((size_t)b * KVH + kh) * TT + t) * HDIM + d;
        v[base]     = to_tf32(e);
        v[base + 1] = to_tf32(o);
    }
}

// ---------------------------------------------------------------------------
// Causal flash attention, tf32 mma + ldmatrix fragments.
// Qs [row][d] s68, Ks [key][d] s68, Vs [d][key] s68 (transposed), Ps [row][key] s68.
// Reduction dims are 64 -> kp loops run 0..3 (16 floats per ldmatrix shot).
// ---------------------------------------------------------------------------
#define FSS 68

__global__ void __launch_bounds__(256) flash_kernel(
    const float* __restrict__ Q, const float* __restrict__ K,
    const float* __restrict__ V, float* __restrict__ Ob)
{
    extern __shared__ float sm[];
    float* Qs = sm;
    float* Ks = Qs + 128 * FSS;
    float* Vs = Ks + 64 * FSS;
    float* Ps = Vs + 64 * FSS;

    const int qt  = blockIdx.x;
    const int bh  = blockIdx.y;
    const int b   = bh / HH;
    const int h   = bh - b * HH;
    const int kvh = h / GG;
    const int tid = threadIdx.x;
    const int w   = tid >> 5;
    const int l   = tid & 31;
    const int g   = l >> 2;
    const int t4  = l & 3;

    const float* qptr = Q + (((size_t)b * HH + h) * TT + (size_t)qt * 128) * HDIM;
    const float* kptr = K + (((size_t)b * KVH + kvh) * TT) * HDIM;
    const float* vptr = V + (((size_t)b * KVH + kvh) * TT) * HDIM;

    const uint32_t smem_u32 = (uint32_t)__cvta_generic_to_shared(sm);
    const uint32_t Ks_off = 128 * FSS * 4;
    const uint32_t Vs_off = Ks_off + 64 * FSS * 4;
    const uint32_t Ps_off = Vs_off + 64 * FSS * 4;

    const int a_row = ((l >> 3) & 1) * 8 + (l & 7);
    const int a_k   = (l >> 4) * 4;
    const uint32_t qa_base = smem_u32 + (uint32_t)(((w * 16 + a_row) * FSS + a_k) * 4);
    const uint32_t pa_base = smem_u32 + Ps_off + (uint32_t)(((w * 16 + a_row) * FSS + a_k) * 4);
    const int b_row = l & 7;
    const int b_k   = (l >> 3) * 4;
    const uint32_t kb_base = smem_u32 + Ks_off + (uint32_t)((b_row * FSS + b_k) * 4);
    const uint32_t vb_base = smem_u32 + Vs_off + (uint32_t)((b_row * FSS + b_k) * 4);

    // Load Q tile 128x64 (pre-rounded)
#pragma unroll
    for (int it = 0; it < 8; it++) {
        int idx = tid + it * 256;
        int row = idx >> 4;
        int dq  = idx & 15;
        *(float4*)&Qs[row * FSS + dq * 4] = *(const float4*)&qptr[row * 64 + dq * 4];
    }

    const int r0 = qt * 128 + w * 16 + g;
    const int r1 = r0 + 8;

    float m0 = -1e30f, m1 = -1e30f, l0 = 0.0f, l1 = 0.0f;
    float o[8][4];
#pragma unroll
    for (int nt = 0; nt < 8; nt++)
#pragma unroll
        for (int r = 0; r < 4; r++) o[nt][r] = 0.0f;

    const float scale = 0.125f;
    const int ktmax = 2 * qt + 1;

    for (int kt = 0; kt <= ktmax; kt++) {
        __syncthreads();
        // K tile: direct copy [key][d]
#pragma unroll
        for (int it = 0; it < 4; it++) {
            int idx = tid + it * 256;
            int row = idx >> 4;
            int dq  = idx & 15;
            *(float4*)&Ks[row * FSS + dq * 4] =
                *(const float4*)&kptr[((size_t)kt * 64 + row) * 64 + dq * 4];
        }
        // V tile: transposed store -> Vs[d][key]
#pragma unroll
        for (int it = 0; it < 2; it++) {
            int idx = tid + it * 256;
            int key = idx & 63;
            int dq  = idx >> 6;
#pragma unroll
            for (int half = 0; half < 2; half++) {
                float4 vv = *(const float4*)&vptr[((size_t)kt * 64 + key) * 64 + dq * 8 + half * 4];
                int d0 = dq * 8 + half * 4;
                Vs[(d0 + 0) * FSS + key] = vv.x;
                Vs[(d0 + 1) * FSS + key] = vv.y;
                Vs[(d0 + 2) * FSS + key] = vv.z;
                Vs[(d0 + 3) * FSS + key] = vv.w;
            }
        }
        __syncthreads();

        if (kt * 64 > qt * 128 + w * 16 + 15) continue;

        // ---- S = Q K^T  (reduce over d = 0..63 -> kp 0..3) ----
        float s[8][4];
#pragma unroll
        for (int nt = 0; nt < 8; nt++)
#pragma unroll
            for (int r = 0; r < 4; r++) s[nt][r] = 0.0f;

#pragma unroll
        for (int kp = 0; kp < 4; kp++) {
            uint32_t bf[8][4];
#pragma unroll
            for (int nt = 0; nt < 8; nt++)
                ldsm_x4(bf[nt][0], bf[nt][1], bf[nt][2], bf[nt][3],
                        kb_base + (uint32_t)((nt * 8 * FSS + kp * 16) * 4));
#pragma unroll
            for (int hh = 0; hh < 2; hh++) {
                const int kb = kp * 16 + hh * 8;
                uint32_t a0, a1, a2, a3;
                ldsm_x4(a0, a1, a2, a3, qa_base + (uint32_t)(kb * 4));
#pragma unroll
                for (int nt = 0; nt < 8; nt++)
                    mma_tf32(s[nt][0], s[nt][1], s[nt][2], s[nt][3],
                             a0, a1, a2, a3, bf[nt][2 * hh], bf[nt][2 * hh + 1]);
            }
        }

        // ---- scale + causal mask ----
        if (kt >= 2 * qt) {
            const int kgb = kt * 64 + 2 * t4;
#pragma unroll
            for (int nt = 0; nt < 8; nt++) {
                int kg = kgb + nt * 8;
                s[nt][0] = (kg     > r0) ? -1e30f : s[nt][0] * scale;
                s[nt][1] = (kg + 1 > r0) ? -1e30f : s[nt][1] * scale;
                s[nt][2] = (kg     > r1) ? -1e30f : s[nt][2] * scale;
                s[nt][3] = (kg + 1 > r1) ? -1e30f : s[nt][3] * scale;
            }
        } else {
#pragma unroll
            for (int nt = 0; nt < 8; nt++) {
                s[nt][0] *= scale; s[nt][1] *= scale;
                s[nt][2] *= scale; s[nt][3] *= scale;
            }
        }

        // ---- online softmax ----
        float rm0 = -1e30f, rm1 = -1e30f;
#pragma unroll
        for (int nt = 0; nt < 8; nt++) {
            rm0 = fmaxf(rm0, fmaxf(s[nt][0], s[nt][1]));
            rm1 = fmaxf(rm1, fmaxf(s[nt][2], s[nt][3]));
        }
        rm0 = fmaxf(rm0, __shfl_xor_sync(0xffffffffu, rm0, 1));
        rm0 = fmaxf(rm0, __shfl_xor_sync(0xffffffffu, rm0, 2));
        rm1 = fmaxf(rm1, __shfl_xor_sync(0xffffffffu, rm1, 1));
        rm1 = fmaxf(rm1, __shfl_xor_sync(0xffffffffu, rm1, 2));

        float nm0 = fmaxf(m0, rm0);
        float nm1 = fmaxf(m1, rm1);
        float al0 = __expf(m0 - nm0);
        float al1 = __expf(m1 - nm1);
        m0 = nm0; m1 = nm1;

        float rs0 = 0.0f, rs1 = 0.0f;
#pragma unroll
        for (int nt = 0; nt < 8; nt++) {
            float p0 = to_tf32(__expf(s[nt][0] - nm0));
            float p1 = to_tf32(__expf(s[nt][1] - nm0));
            float p2 = to_tf32(__expf(s[nt][2] - nm1));
            float p3 = to_tf32(__expf(s[nt][3] - nm1));
            s[nt][0] = p0; s[nt][1] = p1; s[nt][2] = p2; s[nt][3] = p3;
            rs0 += p0 + p1;
            rs1 += p2 + p3;
        }
        rs0 += __shfl_xor_sync(0xffffffffu, rs0, 1);
        rs0 += __shfl_xor_sync(0xffffffffu, rs0, 2);
        rs1 += __shfl_xor_sync(0xffffffffu, rs1, 1);
        rs1 += __shfl_xor_sync(0xffffffffu, rs1, 2);

        l0 = l0 * al0 + rs0;
        l1 = l1 * al1 + rs1;
#pragma unroll
        for (int nt = 0; nt < 8; nt++) {
            o[nt][0] *= al0; o[nt][1] *= al0;
            o[nt][2] *= al1; o[nt][3] *= al1;
        }

        // ---- store P (warp-private rows) ----
#pragma unroll
        for (int nt = 0; nt < 8; nt++) {
            *(float2*)&Ps[(w * 16 + g)     * FSS + nt * 8 + 2 * t4] = make_float2(s[nt][0], s[nt][1]);
            *(float2*)&Ps[(w * 16 + g + 8) * FSS + nt * 8 + 2 * t4] = make_float2(s[nt][2], s[nt][3]);
        }
        __syncwarp();

        // ---- O += P V  (reduce over key = 0..63 -> kp 0..3) ----
#pragma unroll
        for (int kp = 0; kp < 4; kp++) {
            uint32_t bf[8][4];
#pragma unroll
            for (int nt = 0; nt < 8; nt++)
                ldsm_x4(bf[nt][0], bf[nt][1], bf[nt][2], bf[nt][3],
                        vb_base + (uint32_t)((nt * 8 * FSS + kp * 16) * 4));
#pragma unroll
            for (int hh = 0; hh < 2; hh++) {
                const int kb = kp * 16 + hh * 8;
                uint32_t a0, a1, a2, a3;
                ldsm_x4(a0, a1, a2, a3, pa_base + (uint32_t)(kb * 4));
#pragma unroll
                for (int nt = 0; nt < 8; nt++)
                    mma_tf32(o[nt][0], o[nt][1], o[nt][2], o[nt][3],
                             a0, a1, a2, a3, bf[nt][2 * hh], bf[nt][2 * hh + 1]);
            }
        }
    }

    // finalize + tf32-round O (feeds raw-copy out-projection)
    float inv0 = 1.0f / l0;
    float inv1 = 1.0f / l1;
    size_t row0 = (size_t)b * TT + (size_t)qt * 128 + w * 16 + g;
#pragma unroll
    for (int nt = 0; nt < 8; nt++) {
        int col = h * HDIM + nt * 8 + 2 * t4;
        *(float2*)&Ob[row0 * DD + col] =
            make_float2(to_tf32(o[nt][0] * inv0), to_tf32(o[nt][1] * inv0));
        *(float2*)&Ob[(row0 + 8) * DD + col] =
            make_float2(to_tf32(o[nt][2] * inv1), to_tf32(o[nt][3] * inv1));
    }
}

// ---------------------------------------------------------------------------
extern "C" void kernel_launch(void* const* d_in, const int* in_sizes, int n_in,
                              void* d_out, int out_size)
{
    const float* x    = (const float*)d_in[0];
    const float* Wqkv = (const float*)d_in[1];
    const float* Wout = (const float*)d_in[2];
    const float* bout = (const float*)d_in[3];
    const float* rcos = (const float*)d_in[4];
    const float* rsin = (const float*)d_in[5];
    float* out = (float*)d_out;

    float *qkv, *q, *k, *v, *attn, *x32, *wqkvT, *woutT;
    cudaGetSymbolAddress((void**)&qkv,   g_qkv);
    cudaGetSymbolAddress((void**)&q,     g_q);
    cudaGetSymbolAddress((void**)&k,     g_k);
    cudaGetSymbolAddress((void**)&v,     g_v);
    cudaGetSymbolAddress((void**)&attn,  g_attn);
    cudaGetSymbolAddress((void**)&x32,   g_x32);
    cudaGetSymbolAddress((void**)&wqkvT, g_wqkvT);
    cudaGetSymbolAddress((void**)&woutT, g_woutT);

    // 0. Prep: round x; round+transpose weights into [N][K]
    round_tf32_kernel<<<1184, 256>>>(x, x32, (MM * DD) / 4);
    transpose_round_kernel<<<dim3(NQKV / 32, DD / 32), dim3(32, 8)>>>(Wqkv, wqkvT, DD, NQKV);
    transpose_round_kernel<<<dim3(DD / 32, DD / 32),   dim3(32, 8)>>>(Wout, woutT, DD, DD);

    const int gemm_smem = 3 * STAGE_F * sizeof(float);   // 110592 B

    // 1. QKV projection
    {
        cudaFuncSetAttribute(mma_gemm_kernel<0>, cudaFuncAttributeMaxDynamicSharedMemorySize, gemm_smem);
        dim3 grid(NQKV / 128, MM / 128);
        mma_gemm_kernel<0><<<grid, 256, gemm_smem>>>(x32, wqkvT, qkv, nullptr, MM, NQKV, DD);
    }

    // 2. RoPE + split (tf32-rounded outputs)
    {
        int tot = MM * (NQKV / 2);
        rope_split_kernel<<<(tot + 255) / 256, 256>>>(qkv, rcos, rsin, q, k, v);
    }

    // 3. Causal flash attention
    {
        int smem = (128 + 64 + 64 + 128) * FSS * sizeof(float);   // 104448 B
        cudaFuncSetAttribute(flash_kernel, cudaFuncAttributeMaxDynamicSharedMemorySize, smem);
        dim3 grid(TT / 128, BB * HH);
        flash_kernel<<<grid, 256, smem>>>(q, k, v, attn);
    }

    // 4. Out projection + bias + nan_to_num
    {
        cudaFuncSetAttribute(mma_gemm_kernel<1>, cudaFuncAttributeMaxDynamicSharedMemorySize, gemm_smem);
        dim3 grid(DD / 128, MM / 128);
        mma_gemm_kernel<1><<<grid, 256, gemm_smem>>>(attn, woutT, out, bout, MM, DD, DD);
    }
}

// round 14
// speedup vs baseline: 3.7872x; 1.0395x over previous
#include <cuda_runtime.h>
#include <cuda_bf16.h>
#include <math.h>
#include <stdint.h>

// Problem constants
#define BB 2
#define TT 2048
#define DD 2048
#define HH 32
#define KVH 8
#define HDIM 64
#define GG 4
#define NQKV 3072
#define MM (BB*TT)

// ---------------- scratch ----------
__device__ float g_qkv[MM * NQKV];
__device__ float g_q[(size_t)BB * HH * TT * HDIM];
__device__ float g_k[(size_t)BB * KVH * TT * HDIM];
__device__ float g_v[(size_t)BB * KVH * TT * HDIM];     // TRANSPOSED: [b][kvh][d][t]
__device__ float g_attn[(size_t)MM * DD];
__device__ float g_x32[(size_t)MM * DD];
__device__ float g_wqkvT[(size_t)NQKV * DD];
__device__ float g_woutT[(size_t)DD * DD];

__device__ __forceinline__ float nan_clamp(float x) {
    if (isnan(x)) return 0.0f;
    if (isinf(x)) return x > 0.0f ? 10000.0f : -10000.0f;
    return x;
}

__device__ __forceinline__ float to_tf32(float x) {
    uint32_t u;
    asm("cvt.rna.tf32.f32 %0, %1;" : "=r"(u) : "f"(x));
    return __uint_as_float(u);
}

__device__ __forceinline__ void mma_tf32(float& c0, float& c1, float& c2, float& c3,
                                         uint32_t a0, uint32_t a1, uint32_t a2, uint32_t a3,
                                         uint32_t b0, uint32_t b1) {
    asm volatile(
        "mma.sync.aligned.m16n8k8.row.col.f32.tf32.tf32.f32 "
        "{%0,%1,%2,%3}, {%4,%5,%6,%7}, {%8,%9}, {%0,%1,%2,%3};\n"
        : "+f"(c0), "+f"(c1), "+f"(c2), "+f"(c3)
        : "r"(a0), "r"(a1), "r"(a2), "r"(a3), "r"(b0), "r"(b1));
}

__device__ __forceinline__ void ldsm_x4(uint32_t& r0, uint32_t& r1, uint32_t& r2, uint32_t& r3,
                                        uint32_t saddr) {
    asm volatile("ldmatrix.sync.aligned.m8n8.x4.shared.b16 {%0,%1,%2,%3}, [%4];\n"
                 : "=r"(r0), "=r"(r1), "=r"(r2), "=r"(r3) : "r"(saddr) : "memory");
}

__device__ __forceinline__ void cp_async16(uint32_t smem_dst, const void* gmem_src) {
    asm volatile("cp.async.cg.shared.global [%0], [%1], 16;\n" :: "r"(smem_dst), "l"(gmem_src));
}

template<int N> __device__ __forceinline__ void cp_wait() {
    asm volatile("cp.async.wait_group %0;\n" :: "n"(N) : "memory");
}

// ---------------------------------------------------------------------------
// Prep kernels
// ---------------------------------------------------------------------------
__global__ void round_tf32_kernel(const float* __restrict__ in, float* __restrict__ out, int n4)
{
    int stride = gridDim.x * blockDim.x;
    for (int i = blockIdx.x * blockDim.x + threadIdx.x; i < n4; i += stride) {
        float4 v = ((const float4*)in)[i];
        v.x = to_tf32(v.x); v.y = to_tf32(v.y);
        v.z = to_tf32(v.z); v.w = to_tf32(v.w);
        ((float4*)out)[i] = v;
    }
}

__global__ void transpose_round_kernel(const float* __restrict__ in, float* __restrict__ out,
                                       int K, int N)
{
    __shared__ float tile[32][33];
    int k0 = blockIdx.y * 32;
    int n0 = blockIdx.x * 32;
    int tx = threadIdx.x;
    int ty = threadIdx.y;
#pragma unroll
    for (int j = 0; j < 4; j++) {
        int kk = ty + j * 8;
        tile[kk][tx] = to_tf32(in[(size_t)(k0 + kk) * N + n0 + tx]);
    }
    __syncthreads();
#pragma unroll
    for (int j = 0; j < 4; j++) {
        int nn = ty + j * 8;
        out[(size_t)(n0 + nn) * K + k0 + tx] = tile[tx][nn];
    }
}

// ---------------------------------------------------------------------------
// TF32 GEMM (R11-proven): C = A[M,K] @ Bt[N,K]^T, 128x128 tile, BK=32,
// 3-stage cp.async ring, ldmatrix fragments.
// ---------------------------------------------------------------------------
#define TS 36
#define STAGE_F (2 * 128 * TS)

template <int EPI>
__global__ void __launch_bounds__(256, 2) mma_gemm_kernel(
    const float* __restrict__ A, const float* __restrict__ Bt,
    float* __restrict__ C, const float* __restrict__ bias,
    int Md, int Nd, int Kd)
{
    extern __shared__ float smem[];

    const int tid = threadIdx.x;
    const int m0 = blockIdx.y * 128;
    const int n0 = blockIdx.x * 128;

    const int w  = tid >> 5;
    const int l  = tid & 31;
    const int wm = (w >> 2) * 64;
    const int wn = (w & 3) * 32;
    const int g  = l >> 2;
    const int t4 = l & 3;

    const uint32_t smem_u32 = (uint32_t)__cvta_generic_to_shared(smem);
    const int a_row = ((l >> 3) & 1) * 8 + (l & 7);
    const int a_k   = (l >> 4) * 4;
    const uint32_t a_base = (uint32_t)(((wm + a_row) * TS + a_k) * 4);
    const int b_row = l & 7;
    const int b_k   = (l >> 3) * 4;
    const uint32_t b_base = (uint32_t)((128 * TS + (wn + b_row) * TS + b_k) * 4);

    float acc[4][4][4];
#pragma unroll
    for (int mt = 0; mt < 4; mt++)
#pragma unroll
        for (int nt = 0; nt < 4; nt++)
#pragma unroll
            for (int r = 0; r < 4; r++) acc[mt][nt][r] = 0.0f;

    const int nk = Kd >> 5;

    auto issue_stage = [&](int k0, int s) {
        float* As = smem + s * STAGE_F;
        float* Bs = As + 128 * TS;
        uint32_t As_u = (uint32_t)__cvta_generic_to_shared(As);
        uint32_t Bs_u = (uint32_t)__cvta_generic_to_shared(Bs);
#pragma unroll
        for (int it = 0; it < 4; it++) {
            int idx = tid + it * 256;
            int m   = idx >> 3;
            int kq  = idx & 7;
            cp_async16(As_u + (uint32_t)((m * TS + kq * 4) * 4), &A[(size_t)(m0 + m) * Kd + k0 + kq * 4]);
        }
#pragma unroll
        for (int it = 0; it < 4; it++) {
            int idx = tid + it * 256;
            int n   = idx >> 3;
            int kq  = idx & 7;
            cp_async16(Bs_u + (uint32_t)((n * TS + kq * 4) * 4), &Bt[(size_t)(n0 + n) * Kd + k0 + kq * 4]);
        }
        asm volatile("cp.async.commit_group;\n");
    };

    issue_stage(0, 0);
    issue_stage(32, 1);

    for (int k = 0; k < nk; k++) {
        cp_wait<1>();
        __syncthreads();

        if (k + 2 < nk) issue_stage((k + 2) << 5, (k + 2) % 3);

        const uint32_t stage = smem_u32 + (uint32_t)((k % 3) * STAGE_F * 4);
        const uint32_t a_addr = stage + a_base;
        const uint32_t b_addr = stage + b_base;

#pragma unroll
        for (int kp = 0; kp < 2; kp++) {
            uint32_t bf[4][4];
#pragma unroll
            for (int nt = 0; nt < 4; nt++)
                ldsm_x4(bf[nt][0], bf[nt][1], bf[nt][2], bf[nt][3],
                        b_addr + (uint32_t)((nt * 8 * TS + kp * 16) * 4));
#pragma unroll
            for (int h = 0; h < 2; h++) {
                const int kb = kp * 16 + h * 8;
                uint32_t af[4][4];
#pragma unroll
                for (int mt = 0; mt < 4; mt++)
                    ldsm_x4(af[mt][0], af[mt][1], af[mt][2], af[mt][3],
                            a_addr + (uint32_t)((mt * 16 * TS + kb) * 4));
#pragma unroll
                for (int mt = 0; mt < 4; mt++)
#pragma unroll
                    for (int nt = 0; nt < 4; nt++)
                        mma_tf32(acc[mt][nt][0], acc[mt][nt][1], acc[mt][nt][2], acc[mt][nt][3],
                                 af[mt][0], af[mt][1], af[mt][2], af[mt][3],
                                 bf[nt][2 * h], bf[nt][2 * h + 1]);
            }
        }
    }

#pragma unroll
    for (int mt = 0; mt < 4; mt++) {
#pragma unroll
        for (int nt = 0; nt < 4; nt++) {
            int row = m0 + wm + mt * 16 + g;
            int col = n0 + wn + nt * 8 + 2 * t4;
            float2 v0 = make_float2(acc[mt][nt][0], acc[mt][nt][1]);
            float2 v1 = make_float2(acc[mt][nt][2], acc[mt][nt][3]);
            if (EPI) {
                v0.x = nan_clamp(v0.x + bias[col]);
                v0.y = nan_clamp(v0.y + bias[col + 1]);
                v1.x = nan_clamp(v1.x + bias[col]);
                v1.y = nan_clamp(v1.y + bias[col + 1]);
            }
            *(float2*)&C[(size_t)row * Nd + col]       = v0;
            *(float2*)&C[(size_t)(row + 8) * Nd + col] = v1;
        }
    }
}

// ---------------------------------------------------------------------------
// RoPE + split; tf32-rounded outputs. V is written TRANSPOSED: [b][kvh][d][t].
// ---------------------------------------------------------------------------
__global__ void rope_split_kernel(
    const float* __restrict__ qkv,
    const float* __restrict__ rcos, const float* __restrict__ rsin,
    float* __restrict__ q, float* __restrict__ k, float* __restrict__ v)
{
    int idx = blockIdx.x * blockDim.x + threadIdx.x;
    const int TOT = MM * (NQKV / 2);
    if (idx >= TOT) return;
    int m  = idx / (NQKV / 2);
    int c2 = idx - m * (NQKV / 2);
    int c  = c2 * 2;
    int b = m >> 11;
    int t = m & (TT - 1);

    float e = qkv[(size_t)m * NQKV + c];
    float o = qkv[(size_t)m * NQKV + c + 1];
    int d = c & (HDIM - 1);
    int i = d >> 1;

    if (c < HH * HDIM) {
        int h = c >> 6;
        float cs = rcos[t * (HDIM / 2) + i];
        float sn = rsin[t * (HDIM / 2) + i];
        size_t base = (((size_t)b * HH + h) * TT + t) * HDIM + d;
        q[base]     = to_tf32(e * cs - o * sn);
        q[base + 1] = to_tf32(e * sn + o * cs);
    } else if (c < HH * HDIM + KVH * HDIM) {
        int kh = (c - HH * HDIM) >> 6;
        float cs = rcos[t * (HDIM / 2) + i];
        float sn = rsin[t * (HDIM / 2) + i];
        size_t base = (((size_t)b * KVH + kh) * TT + t) * HDIM + d;
        k[base]     = to_tf32(e * cs - o * sn);
        k[base + 1] = to_tf32(e * sn + o * cs);
    } else {
        int kh = (c - HH * HDIM - KVH * HDIM) >> 6;
        // transposed: v[((b*KVH+kh)*HDIM + d)*TT + t]
        size_t base = (((size_t)b * KVH + kh) * HDIM + d) * TT + t;
        v[base]      = to_tf32(e);
        v[base + TT] = to_tf32(o);
    }
}

// ---------------------------------------------------------------------------
// Causal flash attention: 512 threads, 256-q-row tile, 64-key tiles,
// double-buffered cp.async K/V (V pre-transposed in gmem), tf32 mma.
// smem: Qs[256][68] | Ks[2][64][68] | Vs[2][64][68] | Ps[256][68]
// ---------------------------------------------------------------------------
#define FSS 68
#define FQ 256
#define QS_F   (FQ * FSS)          // 17408
#define KV_F   (64 * FSS)          // 4352
#define KS0_F  QS_F
#define VS0_F  (QS_F + 2 * KV_F)
#define PS0_F  (QS_F + 4 * KV_F)
#define FL_SMEM ((QS_F + 4 * KV_F + QS_F) * 4)   // 208896 B

__global__ void __launch_bounds__(512, 1) flash_kernel(
    const float* __restrict__ Q, const float* __restrict__ K,
    const float* __restrict__ Vt, float* __restrict__ Ob)
{
    extern __shared__ float sm[];

    const int qt  = blockIdx.x;                 // 0..7
    const int bh  = blockIdx.y;
    const int b   = bh / HH;
    const int h   = bh - b * HH;
    const int kvh = h / GG;
    const int tid = threadIdx.x;
    const int w   = tid >> 5;                   // 0..15
    const int l   = tid & 31;
    const int g   = l >> 2;
    const int t4  = l & 3;

    const float* qptr  = Q  + (((size_t)b * HH + h) * TT + (size_t)qt * FQ) * HDIM;
    const float* kptr  = K  + (((size_t)b * KVH + kvh) * TT) * HDIM;
    const float* vtptr = Vt + (((size_t)b * KVH + kvh) * HDIM) * TT;

    const uint32_t smem_u32 = (uint32_t)__cvta_generic_to_shared(sm);

    const int a_row = ((l >> 3) & 1) * 8 + (l & 7);
    const int a_k   = (l >> 4) * 4;
    const uint32_t qa_base = smem_u32 + (uint32_t)(((w * 16 + a_row) * FSS + a_k) * 4);
    const uint32_t pa_base = smem_u32 + (uint32_t)((PS0_F + (w * 16 + a_row) * FSS + a_k) * 4);
    const int b_row = l & 7;
    const int b_k   = (l >> 3) * 4;

    // ---- issue Q + tile 0 (group 0) ----
#pragma unroll
    for (int it = 0; it < 8; it++) {
        int idx = tid + it * 512;               // 0..4095
        int row = idx >> 4;
        int dq  = idx & 15;
        cp_async16(smem_u32 + (uint32_t)((row * FSS + dq * 4) * 4),
                   &qptr[row * 64 + dq * 4]);
    }
    {
        // K tile 0 -> buf 0; V tile 0 -> buf 0
#pragma unroll
        for (int it = 0; it < 2; it++) {
            int idx = tid + it * 512;           // 0..1023
            int row = idx >> 4;
            int dq  = idx & 15;
            cp_async16(smem_u32 + (uint32_t)((KS0_F + row * FSS + dq * 4) * 4),
                       &kptr[(size_t)row * 64 + dq * 4]);
            cp_async16(smem_u32 + (uint32_t)((VS0_F + row * FSS + dq * 4) * 4),
                       &vtptr[(size_t)row * TT + dq * 4]);
        }
        asm volatile("cp.async.commit_group;\n");
    }

    const int r0 = qt * FQ + w * 16 + g;
    const int r1 = r0 + 8;

    float m0 = -1e30f, m1 = -1e30f, l0 = 0.0f, l1 = 0.0f;
    float o[8][4];
#pragma unroll
    for (int nt = 0; nt < 8; nt++)
#pragma unroll
        for (int r = 0; r < 4; r++) o[nt][r] = 0.0f;

    const float scale = 0.125f;
    const int ktmax = 4 * qt + 3;

    for (int kt = 0; kt <= ktmax; kt++) {
        __syncthreads();    // all warps done with tile kt-1 (frees buf (kt+1)&1)

        if (kt < ktmax) {
            int nkt = kt + 1;
            uint32_t kb = smem_u32 + (uint32_t)((KS0_F + (nkt & 1) * KV_F) * 4);
            uint32_t vb = smem_u32 + (uint32_t)((VS0_F + (nkt & 1) * KV_F) * 4);
#pragma unroll
            for (int it = 0; it < 2; it++) {
                int idx = tid + it * 512;
                int row = idx >> 4;
                int dq  = idx & 15;
                cp_async16(kb + (uint32_t)((row * FSS + dq * 4) * 4),
                           &kptr[((size_t)nkt * 64 + row) * 64 + dq * 4]);
                cp_async16(vb + (uint32_t)((row * FSS + dq * 4) * 4),
                           &vtptr[(size_t)row * TT + nkt * 64 + dq * 4]);
            }
            asm volatile("cp.async.commit_group;\n");
            cp_wait<1>();
        } else {
            cp_wait<0>();
        }
        __syncthreads();    // tile kt visible to all warps

        if (kt * 64 > qt * FQ + w * 16 + 15) continue;

        const uint32_t kb_base = smem_u32 + (uint32_t)((KS0_F + (kt & 1) * KV_F) * 4)
                                 + (uint32_t)((b_row * FSS + b_k) * 4);
        const uint32_t vb_base = smem_u32 + (uint32_t)((VS0_F + (kt & 1) * KV_F) * 4)
                                 + (uint32_t)((b_row * FSS + b_k) * 4);

        // ---- S = Q K^T ----
        float s[8][4];
#pragma unroll
        for (int nt = 0; nt < 8; nt++)
#pragma unroll
            for (int r = 0; r < 4; r++) s[nt][r] = 0.0f;

#pragma unroll
        for (int kp = 0; kp < 4; kp++) {
            uint32_t bf[8][4];
#pragma unroll
            for (int nt = 0; nt < 8; nt++)
                ldsm_x4(bf[nt][0], bf[nt][1], bf[nt][2], bf[nt][3],
                        kb_base + (uint32_t)((nt * 8 * FSS + kp * 16) * 4));
#pragma unroll
            for (int hh = 0; hh < 2; hh++) {
                const int kb = kp * 16 + hh * 8;
                uint32_t a0, a1, a2, a3;
                ldsm_x4(a0, a1, a2, a3, qa_base + (uint32_t)(kb * 4));
#pragma unroll
                for (int nt = 0; nt < 8; nt++)
                    mma_tf32(s[nt][0], s[nt][1], s[nt][2], s[nt][3],
                             a0, a1, a2, a3, bf[nt][2 * hh], bf[nt][2 * hh + 1]);
            }
        }

        // ---- scale + causal mask ----
        if (kt >= 4 * qt) {
            const int kgb = kt * 64 + 2 * t4;
#pragma unroll
            for (int nt = 0; nt < 8; nt++) {
                int kg = kgb + nt * 8;
                s[nt][0] = (kg     > r0) ? -1e30f : s[nt][0] * scale;
                s[nt][1] = (kg + 1 > r0) ? -1e30f : s[nt][1] * scale;
                s[nt][2] = (kg     > r1) ? -1e30f : s[nt][2] * scale;
                s[nt][3] = (kg + 1 > r1) ? -1e30f : s[nt][3] * scale;
            }
        } else {
#pragma unroll
            for (int nt = 0; nt < 8; nt++) {
                s[nt][0] *= scale; s[nt][1] *= scale;
                s[nt][2] *= scale; s[nt][3] *= scale;
            }
        }

        // ---- online softmax ----
        float rm0 = -1e30f, rm1 = -1e30f;
#pragma unroll
        for (int nt = 0; nt < 8; nt++) {
            rm0 = fmaxf(rm0, fmaxf(s[nt][0], s[nt][1]));
            rm1 = fmaxf(rm1, fmaxf(s[nt][2], s[nt][3]));
        }
        rm0 = fmaxf(rm0, __shfl_xor_sync(0xffffffffu, rm0, 1));
        rm0 = fmaxf(rm0, __shfl_xor_sync(0xffffffffu, rm0, 2));
        rm1 = fmaxf(rm1, __shfl_xor_sync(0xffffffffu, rm1, 1));
        rm1 = fmaxf(rm1, __shfl_xor_sync(0xffffffffu, rm1, 2));

        float nm0 = fmaxf(m0, rm0);
        float nm1 = fmaxf(m1, rm1);
        float al0 = __expf(m0 - nm0);
        float al1 = __expf(m1 - nm1);
        m0 = nm0; m1 = nm1;

        float rs0 = 0.0f, rs1 = 0.0f;
#pragma unroll
        for (int nt = 0; nt < 8; nt++) {
            float p0 = to_tf32(__expf(s[nt][0] - nm0));
            float p1 = to_tf32(__expf(s[nt][1] - nm0));
            float p2 = to_tf32(__expf(s[nt][2] - nm1));
            float p3 = to_tf32(__expf(s[nt][3] - nm1));
            s[nt][0] = p0; s[nt][1] = p1; s[nt][2] = p2; s[nt][3] = p3;
            rs0 += p0 + p1;
            rs1 += p2 + p3;
        }
        rs0 += __shfl_xor_sync(0xffffffffu, rs0, 1);
        rs0 += __shfl_xor_sync(0xffffffffu, rs0, 2);
        rs1 += __shfl_xor_sync(0xffffffffu, rs1, 1);
        rs1 += __shfl_xor_sync(0xffffffffu, rs1, 2);

        l0 = l0 * al0 + rs0;
        l1 = l1 * al1 + rs1;
#pragma unroll
        for (int nt = 0; nt < 8; nt++) {
            o[nt][0] *= al0; o[nt][1] *= al0;
            o[nt][2] *= al1; o[nt][3] *= al1;
        }

        // ---- store P (warp-private rows) ----
        float* Ps = sm + PS0_F;
#pragma unroll
        for (int nt = 0; nt < 8; nt++) {
            *(float2*)&Ps[(w * 16 + g)     * FSS + nt * 8 + 2 * t4] = make_float2(s[nt][0], s[nt][1]);
            *(float2*)&Ps[(w * 16 + g + 8) * FSS + nt * 8 + 2 * t4] = make_float2(s[nt][2], s[nt][3]);
        }
        __syncwarp();

        // ---- O += P V ----
#pragma unroll
        for (int kp = 0; kp < 4; kp++) {
            uint32_t bf[8][4];
#pragma unroll
            for (int nt = 0; nt < 8; nt++)
                ldsm_x4(bf[nt][0], bf[nt][1], bf[nt][2], bf[nt][3],
                        vb_base + (uint32_t)((nt * 8 * FSS + kp * 16) * 4));
#pragma unroll
            for (int hh = 0; hh < 2; hh++) {
                const int kb = kp * 16 + hh * 8;
                uint32_t a0, a1, a2, a3;
                ldsm_x4(a0, a1, a2, a3, pa_base + (uint32_t)(kb * 4));
#pragma unroll
                for (int nt = 0; nt < 8; nt++)
                    mma_tf32(o[nt][0], o[nt][1], o[nt][2], o[nt][3],
                             a0, a1, a2, a3, bf[nt][2 * hh], bf[nt][2 * hh + 1]);
            }
        }
    }

    // finalize + tf32-round O
    float inv0 = 1.0f / l0;
    float inv1 = 1.0f / l1;
    size_t row0 = (size_t)b * TT + (size_t)qt * FQ + w * 16 + g;
#pragma unroll
    for (int nt = 0; nt < 8; nt++) {
        int col = h * HDIM + nt * 8 + 2 * t4;
        *(float2*)&Ob[row0 * DD + col] =
            make_float2(to_tf32(o[nt][0] * inv0), to_tf32(o[nt][1] * inv0));
        *(float2*)&Ob[(row0 + 8) * DD + col] =
            make_float2(to_tf32(o[nt][2] * inv1), to_tf32(o[nt][3] * inv1));
    }
}

// ---------------------------------------------------------------------------
extern "C" void kernel_launch(void* const* d_in, const int* in_sizes, int n_in,
                              void* d_out, int out_size)
{
    const float* x    = (const float*)d_in[0];
    const float* Wqkv = (const float*)d_in[1];
    const float* Wout = (const float*)d_in[2];
    const float* bout = (const float*)d_in[3];
    const float* rcos = (const float*)d_in[4];
    const float* rsin = (const float*)d_in[5];
    float* out = (float*)d_out;

    float *qkv, *q, *k, *v, *attn, *x32, *wqkvT, *woutT;
    cudaGetSymbolAddress((void**)&qkv,   g_qkv);
    cudaGetSymbolAddress((void**)&q,     g_q);
    cudaGetSymbolAddress((void**)&k,     g_k);
    cudaGetSymbolAddress((void**)&v,     g_v);
    cudaGetSymbolAddress((void**)&attn,  g_attn);
    cudaGetSymbolAddress((void**)&x32,   g_x32);
    cudaGetSymbolAddress((void**)&wqkvT, g_wqkvT);
    cudaGetSymbolAddress((void**)&woutT, g_woutT);

    // 0. Prep
    round_tf32_kernel<<<1184, 256>>>(x, x32, (MM * DD) / 4);
    transpose_round_kernel<<<dim3(NQKV / 32, DD / 32), dim3(32, 8)>>>(Wqkv, wqkvT, DD, NQKV);
    transpose_round_kernel<<<dim3(DD / 32, DD / 32),   dim3(32, 8)>>>(Wout, woutT, DD, DD);

    const int gemm_smem = 3 * STAGE_F * sizeof(float);   // 110592 B

    // 1. QKV projection
    {
        cudaFuncSetAttribute(mma_gemm_kernel<0>, cudaFuncAttributeMaxDynamicSharedMemorySize, gemm_smem);
        dim3 grid(NQKV / 128, MM / 128);
        mma_gemm_kernel<0><<<grid, 256, gemm_smem>>>(x32, wqkvT, qkv, nullptr, MM, NQKV, DD);
    }

    // 2. RoPE + split (V transposed)
    {
        int tot = MM * (NQKV / 2);
        rope_split_kernel<<<(tot + 255) / 256, 256>>>(qkv, rcos, rsin, q, k, v);
    }

    // 3. Causal flash attention (pipelined)
    {
        cudaFuncSetAttribute(flash_kernel, cudaFuncAttributeMaxDynamicSharedMemorySize, FL_SMEM);
        dim3 grid(TT / FQ, BB * HH);
        flash_kernel<<<grid, 512, FL_SMEM>>>(q, k, v, attn);
    }

    // 4. Out projection + bias + nan_to_num
    {
        cudaFuncSetAttribute(mma_gemm_kernel<1>, cudaFuncAttributeMaxDynamicSharedMemorySize, gemm_smem);
        dim3 grid(DD / 128, MM / 128);
        mma_gemm_kernel<1><<<grid, 256, gemm_smem>>>(attn, woutT, out, bout, MM, DD, DD);
    }
}

// round 15
// speedup vs baseline: 3.8761x; 1.0235x over previous
#include <cuda_runtime.h>
#include <cuda_bf16.h>
#include <math.h>
#include <stdint.h>

// Problem constants
#define BB 2
#define TT 2048
#define DD 2048
#define HH 32
#define KVH 8
#define HDIM 64
#define GG 4
#define NQKV 3072
#define MM (BB*TT)

// ---------------- scratch ----------
__device__ float g_qkv[MM * NQKV];
__device__ float g_q[(size_t)BB * HH * TT * HDIM];
__device__ float g_k[(size_t)BB * KVH * TT * HDIM];
__device__ float g_v[(size_t)BB * KVH * TT * HDIM];     // TRANSPOSED: [b][kvh][d][t]
__device__ float g_attn[(size_t)MM * DD];
__device__ float g_x32[(size_t)MM * DD];
__device__ float g_wqkvT[(size_t)NQKV * DD];
__device__ float g_woutT[(size_t)DD * DD];

__device__ __forceinline__ float nan_clamp(float x) {
    if (isnan(x)) return 0.0f;
    if (isinf(x)) return x > 0.0f ? 10000.0f : -10000.0f;
    return x;
}

__device__ __forceinline__ float to_tf32(float x) {
    uint32_t u;
    asm("cvt.rna.tf32.f32 %0, %1;" : "=r"(u) : "f"(x));
    return __uint_as_float(u);
}

__device__ __forceinline__ void mma_tf32(float& c0, float& c1, float& c2, float& c3,
                                         uint32_t a0, uint32_t a1, uint32_t a2, uint32_t a3,
                                         uint32_t b0, uint32_t b1) {
    asm volatile(
        "mma.sync.aligned.m16n8k8.row.col.f32.tf32.tf32.f32 "
        "{%0,%1,%2,%3}, {%4,%5,%6,%7}, {%8,%9}, {%0,%1,%2,%3};\n"
        : "+f"(c0), "+f"(c1), "+f"(c2), "+f"(c3)
        : "r"(a0), "r"(a1), "r"(a2), "r"(a3), "r"(b0), "r"(b1));
}

__device__ __forceinline__ void ldsm_x4(uint32_t& r0, uint32_t& r1, uint32_t& r2, uint32_t& r3,
                                        uint32_t saddr) {
    asm volatile("ldmatrix.sync.aligned.m8n8.x4.shared.b16 {%0,%1,%2,%3}, [%4];\n"
                 : "=r"(r0), "=r"(r1), "=r"(r2), "=r"(r3) : "r"(saddr) : "memory");
}

__device__ __forceinline__ void cp_async16(uint32_t smem_dst, const void* gmem_src) {
    asm volatile("cp.async.cg.shared.global [%0], [%1], 16;\n" :: "r"(smem_dst), "l"(gmem_src));
}

template<int N> __device__ __forceinline__ void cp_wait() {
    asm volatile("cp.async.wait_group %0;\n" :: "n"(N) : "memory");
}

// ---------------------------------------------------------------------------
// Prep kernels
// ---------------------------------------------------------------------------
__global__ void round_tf32_kernel(const float* __restrict__ in, float* __restrict__ out, int n4)
{
    int stride = gridDim.x * blockDim.x;
    for (int i = blockIdx.x * blockDim.x + threadIdx.x; i < n4; i += stride) {
        float4 v = ((const float4*)in)[i];
        v.x = to_tf32(v.x); v.y = to_tf32(v.y);
        v.z = to_tf32(v.z); v.w = to_tf32(v.w);
        ((float4*)out)[i] = v;
    }
}

__global__ void transpose_round_kernel(const float* __restrict__ in, float* __restrict__ out,
                                       int K, int N)
{
    __shared__ float tile[32][33];
    int k0 = blockIdx.y * 32;
    int n0 = blockIdx.x * 32;
    int tx = threadIdx.x;
    int ty = threadIdx.y;
#pragma unroll
    for (int j = 0; j < 4; j++) {
        int kk = ty + j * 8;
        tile[kk][tx] = to_tf32(in[(size_t)(k0 + kk) * N + n0 + tx]);
    }
    __syncthreads();
#pragma unroll
    for (int j = 0; j < 4; j++) {
        int nn = ty + j * 8;
        out[(size_t)(n0 + nn) * K + k0 + tx] = tile[tx][nn];
    }
}

// ---------------------------------------------------------------------------
// TF32 GEMM: C = A[M,K] @ Bt[N,K]^T.  128x128 CTA tile, BK=32, 3-stage
// cp.async ring, ldmatrix fragments.  NEW: 4 warps, 64x64 warp tiles
// (2m x 2n grid) -> smem fragment traffic 256->192 B/MMA, 32 MMAs per
// ldsm batch.  Accumulation order per element identical to R11/R14.
// ---------------------------------------------------------------------------
#define TS 36
#define STAGE_F (2 * 128 * TS)

template <int EPI>
__global__ void __launch_bounds__(128, 2) mma_gemm_kernel(
    const float* __restrict__ A, const float* __restrict__ Bt,
    float* __restrict__ C, const float* __restrict__ bias,
    int Md, int Nd, int Kd)
{
    extern __shared__ float smem[];

    const int tid = threadIdx.x;
    const int m0 = blockIdx.y * 128;
    const int n0 = blockIdx.x * 128;

    const int w  = tid >> 5;           // 0..3
    const int l  = tid & 31;
    const int wm = (w >> 1) * 64;      // 0 or 64
    const int wn = (w & 1) * 64;       // 0 or 64
    const int g  = l >> 2;
    const int t4 = l & 3;

    const uint32_t smem_u32 = (uint32_t)__cvta_generic_to_shared(smem);
    const int a_row = ((l >> 3) & 1) * 8 + (l & 7);
    const int a_k   = (l >> 4) * 4;
    const uint32_t a_base = (uint32_t)(((wm + a_row) * TS + a_k) * 4);
    const int b_row = l & 7;
    const int b_k   = (l >> 3) * 4;
    const uint32_t b_base = (uint32_t)((128 * TS + (wn + b_row) * TS + b_k) * 4);

    float acc[4][8][4];
#pragma unroll
    for (int mt = 0; mt < 4; mt++)
#pragma unroll
        for (int nt = 0; nt < 8; nt++)
#pragma unroll
            for (int r = 0; r < 4; r++) acc[mt][nt][r] = 0.0f;

    const int nk = Kd >> 5;

    auto issue_stage = [&](int k0, int s) {
        uint32_t As_u = smem_u32 + (uint32_t)(s * STAGE_F * 4);
        uint32_t Bs_u = As_u + (uint32_t)(128 * TS * 4);
#pragma unroll
        for (int it = 0; it < 8; it++) {
            int idx = tid + it * 128;          // 0..1023
            int m   = idx >> 3;
            int kq  = idx & 7;
            cp_async16(As_u + (uint32_t)((m * TS + kq * 4) * 4),
                       &A[(size_t)(m0 + m) * Kd + k0 + kq * 4]);
        }
#pragma unroll
        for (int it = 0; it < 8; it++) {
            int idx = tid + it * 128;
            int n   = idx >> 3;
            int kq  = idx & 7;
            cp_async16(Bs_u + (uint32_t)((n * TS + kq * 4) * 4),
                       &Bt[(size_t)(n0 + n) * Kd + k0 + kq * 4]);
        }
        asm volatile("cp.async.commit_group;\n");
    };

    issue_stage(0, 0);
    issue_stage(32, 1);

    for (int k = 0; k < nk; k++) {
        cp_wait<1>();
        __syncthreads();

        if (k + 2 < nk) issue_stage((k + 2) << 5, (k + 2) % 3);

        const uint32_t stage = smem_u32 + (uint32_t)((k % 3) * STAGE_F * 4);
        const uint32_t a_addr = stage + a_base;
        const uint32_t b_addr = stage + b_base;

#pragma unroll
        for (int kp = 0; kp < 2; kp++) {
            uint32_t bf[8][4];
#pragma unroll
            for (int nt = 0; nt < 8; nt++)
                ldsm_x4(bf[nt][0], bf[nt][1], bf[nt][2], bf[nt][3],
                        b_addr + (uint32_t)((nt * 8 * TS + kp * 16) * 4));
#pragma unroll
            for (int h = 0; h < 2; h++) {
                const int kb = kp * 16 + h * 8;
                uint32_t af[4][4];
#pragma unroll
                for (int mt = 0; mt < 4; mt++)
                    ldsm_x4(af[mt][0], af[mt][1], af[mt][2], af[mt][3],
                            a_addr + (uint32_t)((mt * 16 * TS + kb) * 4));
#pragma unroll
                for (int mt = 0; mt < 4; mt++)
#pragma unroll
                    for (int nt = 0; nt < 8; nt++)
                        mma_tf32(acc[mt][nt][0], acc[mt][nt][1], acc[mt][nt][2], acc[mt][nt][3],
                                 af[mt][0], af[mt][1], af[mt][2], af[mt][3],
                                 bf[nt][2 * h], bf[nt][2 * h + 1]);
            }
        }
    }

#pragma unroll
    for (int mt = 0; mt < 4; mt++) {
#pragma unroll
        for (int nt = 0; nt < 8; nt++) {
            int row = m0 + wm + mt * 16 + g;
            int col = n0 + wn + nt * 8 + 2 * t4;
            float2 v0 = make_float2(acc[mt][nt][0], acc[mt][nt][1]);
            float2 v1 = make_float2(acc[mt][nt][2], acc[mt][nt][3]);
            if (EPI) {
                v0.x = nan_clamp(v0.x + bias[col]);
                v0.y = nan_clamp(v0.y + bias[col + 1]);
                v1.x = nan_clamp(v1.x + bias[col]);
                v1.y = nan_clamp(v1.y + bias[col + 1]);
            }
            *(float2*)&C[(size_t)row * Nd + col]       = v0;
            *(float2*)&C[(size_t)(row + 8) * Nd + col] = v1;
        }
    }
}

// ---------------------------------------------------------------------------
// RoPE + split; tf32-rounded outputs. V written TRANSPOSED: [b][kvh][d][t].
// ---------------------------------------------------------------------------
__global__ void rope_split_kernel(
    const float* __restrict__ qkv,
    const float* __restrict__ rcos, const float* __restrict__ rsin,
    float* __restrict__ q, float* __restrict__ k, float* __restrict__ v)
{
    int idx = blockIdx.x * blockDim.x + threadIdx.x;
    const int TOT = MM * (NQKV / 2);
    if (idx >= TOT) return;
    int m  = idx / (NQKV / 2);
    int c2 = idx - m * (NQKV / 2);
    int c  = c2 * 2;
    int b = m >> 11;
    int t = m & (TT - 1);

    float e = qkv[(size_t)m * NQKV + c];
    float o = qkv[(size_t)m * NQKV + c + 1];
    int d = c & (HDIM - 1);
    int i = d >> 1;

    if (c < HH * HDIM) {
        int h = c >> 6;
        float cs = rcos[t * (HDIM / 2) + i];
        float sn = rsin[t * (HDIM / 2) + i];
        size_t base = (((size_t)b * HH + h) * TT + t) * HDIM + d;
        q[base]     = to_tf32(e * cs - o * sn);
        q[base + 1] = to_tf32(e * sn + o * cs);
    } else if (c < HH * HDIM + KVH * HDIM) {
        int kh = (c - HH * HDIM) >> 6;
        float cs = rcos[t * (HDIM / 2) + i];
        float sn = rsin[t * (HDIM / 2) + i];
        size_t base = (((size_t)b * KVH + kh) * TT + t) * HDIM + d;
        k[base]     = to_tf32(e * cs - o * sn);
        k[base + 1] = to_tf32(e * sn + o * cs);
    } else {
        int kh = (c - HH * HDIM - KVH * HDIM) >> 6;
        size_t base = (((size_t)b * KVH + kh) * HDIM + d) * TT + t;
        v[base]      = to_tf32(e);
        v[base + TT] = to_tf32(o);
    }
}

// ---------------------------------------------------------------------------
// Causal flash attention: 512 threads, 256-q-row tile, 64-key tiles,
// double-buffered cp.async K/V (V pre-transposed in gmem), tf32 mma.
// ---------------------------------------------------------------------------
#define FSS 68
#define FQ 256
#define QS_F   (FQ * FSS)
#define KV_F   (64 * FSS)
#define KS0_F  QS_F
#define VS0_F  (QS_F + 2 * KV_F)
#define PS0_F  (QS_F + 4 * KV_F)
#define FL_SMEM ((QS_F + 4 * KV_F + QS_F) * 4)   // 208896 B

__global__ void __launch_bounds__(512, 1) flash_kernel(
    const float* __restrict__ Q, const float* __restrict__ K,
    const float* __restrict__ Vt, float* __restrict__ Ob)
{
    extern __shared__ float sm[];

    const int qt  = blockIdx.x;
    const int bh  = blockIdx.y;
    const int b   = bh / HH;
    const int h   = bh - b * HH;
    const int kvh = h / GG;
    const int tid = threadIdx.x;
    const int w   = tid >> 5;
    const int l   = tid & 31;
    const int g   = l >> 2;
    const int t4  = l & 3;

    const float* qptr  = Q  + (((size_t)b * HH + h) * TT + (size_t)qt * FQ) * HDIM;
    const float* kptr  = K  + (((size_t)b * KVH + kvh) * TT) * HDIM;
    const float* vtptr = Vt + (((size_t)b * KVH + kvh) * HDIM) * TT;

    const uint32_t smem_u32 = (uint32_t)__cvta_generic_to_shared(sm);

    const int a_row = ((l >> 3) & 1) * 8 + (l & 7);
    const int a_k   = (l >> 4) * 4;
    const uint32_t qa_base = smem_u32 + (uint32_t)(((w * 16 + a_row) * FSS + a_k) * 4);
    const uint32_t pa_base = smem_u32 + (uint32_t)((PS0_F + (w * 16 + a_row) * FSS + a_k) * 4);
    const int b_row = l & 7;
    const int b_k   = (l >> 3) * 4;

#pragma unroll
    for (int it = 0; it < 8; it++) {
        int idx = tid + it * 512;
        int row = idx >> 4;
        int dq  = idx & 15;
        cp_async16(smem_u32 + (uint32_t)((row * FSS + dq * 4) * 4),
                   &qptr[row * 64 + dq * 4]);
    }
    {
#pragma unroll
        for (int it = 0; it < 2; it++) {
            int idx = tid + it * 512;
            int row = idx >> 4;
            int dq  = idx & 15;
            cp_async16(smem_u32 + (uint32_t)((KS0_F + row * FSS + dq * 4) * 4),
                       &kptr[(size_t)row * 64 + dq * 4]);
            cp_async16(smem_u32 + (uint32_t)((VS0_F + row * FSS + dq * 4) * 4),
                       &vtptr[(size_t)row * TT + dq * 4]);
        }
        asm volatile("cp.async.commit_group;\n");
    }

    const int r0 = qt * FQ + w * 16 + g;
    const int r1 = r0 + 8;

    float m0 = -1e30f, m1 = -1e30f, l0 = 0.0f, l1 = 0.0f;
    float o[8][4];
#pragma unroll
    for (int nt = 0; nt < 8; nt++)
#pragma unroll
        for (int r = 0; r < 4; r++) o[nt][r] = 0.0f;

    const float scale = 0.125f;
    const int ktmax = 4 * qt + 3;

    for (int kt = 0; kt <= ktmax; kt++) {
        __syncthreads();

        if (kt < ktmax) {
            int nkt = kt + 1;
            uint32_t kb = smem_u32 + (uint32_t)((KS0_F + (nkt & 1) * KV_F) * 4);
            uint32_t vb = smem_u32 + (uint32_t)((VS0_F + (nkt & 1) * KV_F) * 4);
#pragma unroll
            for (int it = 0; it < 2; it++) {
                int idx = tid + it * 512;
                int row = idx >> 4;
                int dq  = idx & 15;
                cp_async16(kb + (uint32_t)((row * FSS + dq * 4) * 4),
                           &kptr[((size_t)nkt * 64 + row) * 64 + dq * 4]);
                cp_async16(vb + (uint32_t)((row * FSS + dq * 4) * 4),
                           &vtptr[(size_t)row * TT + nkt * 64 + dq * 4]);
            }
            asm volatile("cp.async.commit_group;\n");
            cp_wait<1>();
        } else {
            cp_wait<0>();
        }
        __syncthreads();

        if (kt * 64 > qt * FQ + w * 16 + 15) continue;

        const uint32_t kb_base = smem_u32 + (uint32_t)((KS0_F + (kt & 1) * KV_F) * 4)
                                 + (uint32_t)((b_row * FSS + b_k) * 4);
        const uint32_t vb_base = smem_u32 + (uint32_t)((VS0_F + (kt & 1) * KV_F) * 4)
                                 + (uint32_t)((b_row * FSS + b_k) * 4);

        float s[8][4];
#pragma unroll
        for (int nt = 0; nt < 8; nt++)
#pragma unroll
            for (int r = 0; r < 4; r++) s[nt][r] = 0.0f;

#pragma unroll
        for (int kp = 0; kp < 4; kp++) {
            uint32_t bf[8][4];
#pragma unroll
            for (int nt = 0; nt < 8; nt++)
                ldsm_x4(bf[nt][0], bf[nt][1], bf[nt][2], bf[nt][3],
                        kb_base + (uint32_t)((nt * 8 * FSS + kp * 16) * 4));
#pragma unroll
            for (int hh = 0; hh < 2; hh++) {
                const int kb = kp * 16 + hh * 8;
                uint32_t a0, a1, a2, a3;
                ldsm_x4(a0, a1, a2, a3, qa_base + (uint32_t)(kb * 4));
#pragma unroll
                for (int nt = 0; nt < 8; nt++)
                    mma_tf32(s[nt][0], s[nt][1], s[nt][2], s[nt][3],
                             a0, a1, a2, a3, bf[nt][2 * hh], bf[nt][2 * hh + 1]);
            }
        }

        if (kt >= 4 * qt) {
            const int kgb = kt * 64 + 2 * t4;
#pragma unroll
            for (int nt = 0; nt < 8; nt++) {
                int kg = kgb + nt * 8;
                s[nt][0] = (kg     > r0) ? -1e30f : s[nt][0] * scale;
                s[nt][1] = (kg + 1 > r0) ? -1e30f : s[nt][1] * scale;
                s[nt][2] = (kg     > r1) ? -1e30f : s[nt][2] * scale;
                s[nt][3] = (kg + 1 > r1) ? -1e30f : s[nt][3] * scale;
            }
        } else {
#pragma unroll
            for (int nt = 0; nt < 8; nt++) {
                s[nt][0] *= scale; s[nt][1] *= scale;
                s[nt][2] *= scale; s[nt][3] *= scale;
            }
        }

        float rm0 = -1e30f, rm1 = -1e30f;
#pragma unroll
        for (int nt = 0; nt < 8; nt++) {
            rm0 = fmaxf(rm0, fmaxf(s[nt][0], s[nt][1]));
            rm1 = fmaxf(rm1, fmaxf(s[nt][2], s[nt][3]));
        }
        rm0 = fmaxf(rm0, __shfl_xor_sync(0xffffffffu, rm0, 1));
        rm0 = fmaxf(rm0, __shfl_xor_sync(0xffffffffu, rm0, 2));
        rm1 = fmaxf(rm1, __shfl_xor_sync(0xffffffffu, rm1, 1));
        rm1 = fmaxf(rm1, __shfl_xor_sync(0xffffffffu, rm1, 2));

        float nm0 = fmaxf(m0, rm0);
        float nm1 = fmaxf(m1, rm1);
        float al0 = __expf(m0 - nm0);
        float al1 = __expf(m1 - nm1);
        m0 = nm0; m1 = nm1;

        float rs0 = 0.0f, rs1 = 0.0f;
#pragma unroll
        for (int nt = 0; nt < 8; nt++) {
            float p0 = to_tf32(__expf(s[nt][0] - nm0));
            float p1 = to_tf32(__expf(s[nt][1] - nm0));
            float p2 = to_tf32(__expf(s[nt][2] - nm1));
            float p3 = to_tf32(__expf(s[nt][3] - nm1));
            s[nt][0] = p0; s[nt][1] = p1; s[nt][2] = p2; s[nt][3] = p3;
            rs0 += p0 + p1;
            rs1 += p2 + p3;
        }
        rs0 += __shfl_xor_sync(0xffffffffu, rs0, 1);
        rs0 += __shfl_xor_sync(0xffffffffu, rs0, 2);
        rs1 += __shfl_xor_sync(0xffffffffu, rs1, 1);
        rs1 += __shfl_xor_sync(0xffffffffu, rs1, 2);

        l0 = l0 * al0 + rs0;
        l1 = l1 * al1 + rs1;
#pragma unroll
        for (int nt = 0; nt < 8; nt++) {
            o[nt][0] *= al0; o[nt][1] *= al0;
            o[nt][2] *= al1; o[nt][3] *= al1;
        }

        float* Ps = sm + PS0_F;
#pragma unroll
        for (int nt = 0; nt < 8; nt++) {
            *(float2*)&Ps[(w * 16 + g)     * FSS + nt * 8 + 2 * t4] = make_float2(s[nt][0], s[nt][1]);
            *(float2*)&Ps[(w * 16 + g + 8) * FSS + nt * 8 + 2 * t4] = make_float2(s[nt][2], s[nt][3]);
        }
        __syncwarp();

#pragma unroll
        for (int kp = 0; kp < 4; kp++) {
            uint32_t bf[8][4];
#pragma unroll
            for (int nt = 0; nt < 8; nt++)
                ldsm_x4(bf[nt][0], bf[nt][1], bf[nt][2], bf[nt][3],
                        vb_base + (uint32_t)((nt * 8 * FSS + kp * 16) * 4));
#pragma unroll
            for (int hh = 0; hh < 2; hh++) {
                const int kb = kp * 16 + hh * 8;
                uint32_t a0, a1, a2, a3;
                ldsm_x4(a0, a1, a2, a3, pa_base + (uint32_t)(kb * 4));
#pragma unroll
                for (int nt = 0; nt < 8; nt++)
                    mma_tf32(o[nt][0], o[nt][1], o[nt][2], o[nt][3],
                             a0, a1, a2, a3, bf[nt][2 * hh], bf[nt][2 * hh + 1]);
            }
        }
    }

    float inv0 = 1.0f / l0;
    float inv1 = 1.0f / l1;
    size_t row0 = (size_t)b * TT + (size_t)qt * FQ + w * 16 + g;
#pragma unroll
    for (int nt = 0; nt < 8; nt++) {
        int col = h * HDIM + nt * 8 + 2 * t4;
        *(float2*)&Ob[row0 * DD + col] =
            make_float2(to_tf32(o[nt][0] * inv0), to_tf32(o[nt][1] * inv0));
        *(float2*)&Ob[(row0 + 8) * DD + col] =
            make_float2(to_tf32(o[nt][2] * inv1), to_tf32(o[nt][3] * inv1));
    }
}

// ---------------------------------------------------------------------------
extern "C" void kernel_launch(void* const* d_in, const int* in_sizes, int n_in,
                              void* d_out, int out_size)
{
    const float* x    = (const float*)d_in[0];
    const float* Wqkv = (const float*)d_in[1];
    const float* Wout = (const float*)d_in[2];
    const float* bout = (const float*)d_in[3];
    const float* rcos = (const float*)d_in[4];
    const float* rsin = (const float*)d_in[5];
    float* out = (float*)d_out;

    float *qkv, *q, *k, *v, *attn, *x32, *wqkvT, *woutT;
    cudaGetSymbolAddress((void**)&qkv,   g_qkv);
    cudaGetSymbolAddress((void**)&q,     g_q);
    cudaGetSymbolAddress((void**)&k,     g_k);
    cudaGetSymbolAddress((void**)&v,     g_v);
    cudaGetSymbolAddress((void**)&attn,  g_attn);
    cudaGetSymbolAddress((void**)&x32,   g_x32);
    cudaGetSymbolAddress((void**)&wqkvT, g_wqkvT);
    cudaGetSymbolAddress((void**)&woutT, g_woutT);

    // 0. Prep
    round_tf32_kernel<<<1184, 256>>>(x, x32, (MM * DD) / 4);
    transpose_round_kernel<<<dim3(NQKV / 32, DD / 32), dim3(32, 8)>>>(Wqkv, wqkvT, DD, NQKV);
    transpose_round_kernel<<<dim3(DD / 32, DD / 32),   dim3(32, 8)>>>(Wout, woutT, DD, DD);

    const int gemm_smem = 3 * STAGE_F * sizeof(float);   // 110592 B

    // 1. QKV projection
    {
        cudaFuncSetAttribute(mma_gemm_kernel<0>, cudaFuncAttributeMaxDynamicSharedMemorySize, gemm_smem);
        dim3 grid(NQKV / 128, MM / 128);
        mma_gemm_kernel<0><<<grid, 128, gemm_smem>>>(x32, wqkvT, qkv, nullptr, MM, NQKV, DD);
    }

    // 2. RoPE + split (V transposed)
    {
        int tot = MM * (NQKV / 2);
        rope_split_kernel<<<(tot + 255) / 256, 256>>>(qkv, rcos, rsin, q, k, v);
    }

    // 3. Causal flash attention (pipelined)
    {
        cudaFuncSetAttribute(flash_kernel, cudaFuncAttributeMaxDynamicSharedMemorySize, FL_SMEM);
        dim3 grid(TT / FQ, BB * HH);
        flash_kernel<<<grid, 512, FL_SMEM>>>(q, k, v, attn);
    }

    // 4. Out projection + bias + nan_to_num
    {
        cudaFuncSetAttribute(mma_gemm_kernel<1>, cudaFuncAttributeMaxDynamicSharedMemorySize, gemm_smem);
        dim3 grid(DD / 128, MM / 128);
        mma_gemm_kernel<1><<<grid, 128, gemm_smem>>>(attn, woutT, out, bout, MM, DD, DD);
    }
}

// round 16
// speedup vs baseline: 7.0508x; 1.8190x over previous
#include <cuda_runtime.h>
#include <cuda_fp16.h>
#include <math.h>
#include <stdint.h>

// Problem constants
#define BB 2
#define TT 2048
#define DD 2048
#define HH 32
#define KVH 8
#define HDIM 64
#define GG 4
#define NQKV 3072
#define MM (BB*TT)

// ---------------- scratch ----------
__device__ float  g_qkv[MM * NQKV];                       // fp32 qkv (rope input)
__device__ __half g_x16[(size_t)MM * DD];                 // fp16 x
__device__ __half g_wqkvT16[(size_t)NQKV * DD];           // fp16 W_qkv^T [N][K]
__device__ __half g_woutT16[(size_t)DD * DD];             // fp16 W_out^T [N][K]
__device__ __half g_q16[(size_t)BB * HH * TT * HDIM];
__device__ __half g_k16[(size_t)BB * KVH * TT * HDIM];
__device__ __half g_v16[(size_t)BB * KVH * TT * HDIM];    // TRANSPOSED [b][kvh][d][t]
__device__ __half g_attn16[(size_t)MM * DD];              // fp16 attention output

__device__ __forceinline__ float nan_clamp(float x) {
    if (isnan(x)) return 0.0f;
    if (isinf(x)) return x > 0.0f ? 10000.0f : -10000.0f;
    return x;
}

__device__ __forceinline__ void mma_f16(float& c0, float& c1, float& c2, float& c3,
                                        uint32_t a0, uint32_t a1, uint32_t a2, uint32_t a3,
                                        uint32_t b0, uint32_t b1) {
    asm volatile(
        "mma.sync.aligned.m16n8k16.row.col.f32.f16.f16.f32 "
        "{%0,%1,%2,%3}, {%4,%5,%6,%7}, {%8,%9}, {%0,%1,%2,%3};\n"
        : "+f"(c0), "+f"(c1), "+f"(c2), "+f"(c3)
        : "r"(a0), "r"(a1), "r"(a2), "r"(a3), "r"(b0), "r"(b1));
}

__device__ __forceinline__ void ldsm_x4(uint32_t& r0, uint32_t& r1, uint32_t& r2, uint32_t& r3,
                                        uint32_t saddr) {
    asm volatile("ldmatrix.sync.aligned.m8n8.x4.shared.b16 {%0,%1,%2,%3}, [%4];\n"
                 : "=r"(r0), "=r"(r1), "=r"(r2), "=r"(r3) : "r"(saddr) : "memory");
}

__device__ __forceinline__ void cp_async16(uint32_t smem_dst, const void* gmem_src) {
    asm volatile("cp.async.cg.shared.global [%0], [%1], 16;\n" :: "r"(smem_dst), "l"(gmem_src));
}

template<int N> __device__ __forceinline__ void cp_wait() {
    asm volatile("cp.async.wait_group %0;\n" :: "n"(N) : "memory");
}

// ---------------------------------------------------------------------------
// Prep: fp16 rounding / transpose
// ---------------------------------------------------------------------------
__global__ void round_fp16_kernel(const float* __restrict__ in, __half* __restrict__ out, int n4)
{
    int stride = gridDim.x * blockDim.x;
    for (int i = blockIdx.x * blockDim.x + threadIdx.x; i < n4; i += stride) {
        float4 v = ((const float4*)in)[i];
        __half2 h0 = __floats2half2_rn(v.x, v.y);
        __half2 h1 = __floats2half2_rn(v.z, v.w);
        uint2 u;
        u.x = *(uint32_t*)&h0;
        u.y = *(uint32_t*)&h1;
        ((uint2*)out)[i] = u;
    }
}

// in: [K][N] fp32 -> out: [N][K] fp16
__global__ void transpose_fp16_kernel(const float* __restrict__ in, __half* __restrict__ out,
                                      int K, int N)
{
    __shared__ float tile[32][33];
    int k0 = blockIdx.y * 32;
    int n0 = blockIdx.x * 32;
    int tx = threadIdx.x;
    int ty = threadIdx.y;
#pragma unroll
    for (int j = 0; j < 4; j++) {
        int kk = ty + j * 8;
        tile[kk][tx] = in[(size_t)(k0 + kk) * N + n0 + tx];
    }
    __syncthreads();
#pragma unroll
    for (int j = 0; j < 4; j++) {
        int nn = ty + j * 8;
        out[(size_t)(n0 + nn) * K + k0 + tx] = __float2half_rn(tile[tx][nn]);
    }
}

// ---------------------------------------------------------------------------
// FP16 GEMM: C[M,N](fp32 or epi) = A16[M,K] @ Bt16[N,K]^T
// 128x128 CTA tile, BK=32 halves, 3-stage cp.async ring, 4 warps 64x64 tiles.
// As [128][40] halves, Bs [128][40] halves (stride 80 B: 16B-slot odd -> cf).
// ---------------------------------------------------------------------------
#define TSH 40
#define STAGE_H (2 * 128 * TSH)      // 10240 halves = 20480 B / stage

template <int EPI>
__global__ void __launch_bounds__(128, 2) mma_gemm_f16_kernel(
    const __half* __restrict__ A, const __half* __restrict__ Bt,
    float* __restrict__ C, const float* __restrict__ bias,
    int Md, int Nd, int Kd)
{
    extern __shared__ __half smh[];

    const int tid = threadIdx.x;
    const int m0 = blockIdx.y * 128;
    const int n0 = blockIdx.x * 128;

    const int w  = tid >> 5;           // 0..3
    const int l  = tid & 31;
    const int wm = (w >> 1) * 64;
    const int wn = (w & 1) * 64;
    const int g  = l >> 2;
    const int t4 = l & 3;

    const uint32_t smem_u32 = (uint32_t)__cvta_generic_to_shared(smh);
    // ldmatrix lane constants (byte offsets)
    const int row_a = (l & 7) + ((l >> 3) & 1) * 8;
    const int ka    = (l >> 4) * 8;                  // halves
    const uint32_t a_lane = (uint32_t)((row_a * TSH + ka) * 2);
    const int row_b = (l & 7) + ((l >> 4) << 3);
    const int kb_   = ((l >> 3) & 1) * 8;
    const uint32_t b_lane = (uint32_t)((128 * TSH + row_b * TSH + kb_) * 2);

    float acc[4][8][4];
#pragma unroll
    for (int mt = 0; mt < 4; mt++)
#pragma unroll
        for (int nt = 0; nt < 8; nt++)
#pragma unroll
            for (int r = 0; r < 4; r++) acc[mt][nt][r] = 0.0f;

    const int nk = Kd >> 5;

    auto issue_stage = [&](int k0, int s) {
        uint32_t As_u = smem_u32 + (uint32_t)(s * STAGE_H * 2);
        uint32_t Bs_u = As_u + (uint32_t)(128 * TSH * 2);
        // A: 128 rows x 4 chunks(16B=8 halves) = 512 chunks
#pragma unroll
        for (int it = 0; it < 4; it++) {
            int idx = tid + it * 128;
            int m   = idx >> 2;
            int kq  = idx & 3;
            cp_async16(As_u + (uint32_t)((m * TSH + kq * 8) * 2),
                       &A[(size_t)(m0 + m) * Kd + k0 + kq * 8]);
        }
#pragma unroll
        for (int it = 0; it < 4; it++) {
            int idx = tid + it * 128;
            int n   = idx >> 2;
            int kq  = idx & 3;
            cp_async16(Bs_u + (uint32_t)((n * TSH + kq * 8) * 2),
                       &Bt[(size_t)(n0 + n) * Kd + k0 + kq * 8]);
        }
        asm volatile("cp.async.commit_group;\n");
    };

    issue_stage(0, 0);
    issue_stage(32, 1);

    for (int k = 0; k < nk; k++) {
        cp_wait<1>();
        __syncthreads();

        if (k + 2 < nk) issue_stage((k + 2) << 5, (k + 2) % 3);

        const uint32_t stage = smem_u32 + (uint32_t)((k % 3) * STAGE_H * 2);

#pragma unroll
        for (int kp = 0; kp < 2; kp++) {          // 2 x k16 = BK 32
            uint32_t bf[8][2];
#pragma unroll
            for (int j = 0; j < 4; j++) {
                ldsm_x4(bf[2 * j][0], bf[2 * j][1], bf[2 * j + 1][0], bf[2 * j + 1][1],
                        stage + b_lane + (uint32_t)(((wn + j * 16) * TSH + kp * 16) * 2));
            }
            uint32_t af[4][4];
#pragma unroll
            for (int mt = 0; mt < 4; mt++)
                ldsm_x4(af[mt][0], af[mt][1], af[mt][2], af[mt][3],
                        stage + a_lane + (uint32_t)(((wm + mt * 16) * TSH + kp * 16) * 2));
#pragma unroll
            for (int mt = 0; mt < 4; mt++)
#pragma unroll
                for (int nt = 0; nt < 8; nt++)
                    mma_f16(acc[mt][nt][0], acc[mt][nt][1], acc[mt][nt][2], acc[mt][nt][3],
                            af[mt][0], af[mt][1], af[mt][2], af[mt][3],
                            bf[nt][0], bf[nt][1]);
        }
    }

#pragma unroll
    for (int mt = 0; mt < 4; mt++) {
#pragma unroll
        for (int nt = 0; nt < 8; nt++) {
            int row = m0 + wm + mt * 16 + g;
            int col = n0 + wn + nt * 8 + 2 * t4;
            float2 v0 = make_float2(acc[mt][nt][0], acc[mt][nt][1]);
            float2 v1 = make_float2(acc[mt][nt][2], acc[mt][nt][3]);
            if (EPI) {
                v0.x = nan_clamp(v0.x + bias[col]);
                v0.y = nan_clamp(v0.y + bias[col + 1]);
                v1.x = nan_clamp(v1.x + bias[col]);
                v1.y = nan_clamp(v1.y + bias[col + 1]);
            }
            *(float2*)&C[(size_t)row * Nd + col]       = v0;
            *(float2*)&C[(size_t)(row + 8) * Nd + col] = v1;
        }
    }
}

// ---------------------------------------------------------------------------
// RoPE + split; outputs fp16 q/k, fp16 V TRANSPOSED [b][kvh][d][t].
// ---------------------------------------------------------------------------
__global__ void rope_split_kernel(
    const float* __restrict__ qkv,
    const float* __restrict__ rcos, const float* __restrict__ rsin,
    __half* __restrict__ q, __half* __restrict__ k, __half* __restrict__ v)
{
    int idx = blockIdx.x * blockDim.x + threadIdx.x;
    const int TOT = MM * (NQKV / 2);
    if (idx >= TOT) return;
    int m  = idx / (NQKV / 2);
    int c2 = idx - m * (NQKV / 2);
    int c  = c2 * 2;
    int b = m >> 11;
    int t = m & (TT - 1);

    float e = qkv[(size_t)m * NQKV + c];
    float o = qkv[(size_t)m * NQKV + c + 1];
    int d = c & (HDIM - 1);
    int i = d >> 1;

    if (c < HH * HDIM) {
        int h = c >> 6;
        float cs = rcos[t * (HDIM / 2) + i];
        float sn = rsin[t * (HDIM / 2) + i];
        size_t base = (((size_t)b * HH + h) * TT + t) * HDIM + d;
        *(__half2*)&q[base] = __floats2half2_rn(e * cs - o * sn, e * sn + o * cs);
    } else if (c < HH * HDIM + KVH * HDIM) {
        int kh = (c - HH * HDIM) >> 6;
        float cs = rcos[t * (HDIM / 2) + i];
        float sn = rsin[t * (HDIM / 2) + i];
        size_t base = (((size_t)b * KVH + kh) * TT + t) * HDIM + d;
        *(__half2*)&k[base] = __floats2half2_rn(e * cs - o * sn, e * sn + o * cs);
    } else {
        int kh = (c - HH * HDIM - KVH * HDIM) >> 6;
        size_t base = (((size_t)b * KVH + kh) * HDIM + d) * TT + t;
        v[base]      = __float2half_rn(e);
        v[base + TT] = __float2half_rn(o);
    }
}

// ---------------------------------------------------------------------------
// Causal flash attention, fp16 mma: 512 threads, 256-q-row tile, 64-key
// tiles, double-buffered cp.async K/V. Output fp16.
// smem (halves): Qs[256][72] | Ks[2][64][72] | Vs[2][64][72] | Ps[256][72]
// ---------------------------------------------------------------------------
#define FSH 72
#define FQ 256
#define QS_H   (FQ * FSH)           // 18432
#define KV_H   (64 * FSH)           // 4608
#define KS0_H  QS_H
#define VS0_H  (QS_H + 2 * KV_H)
#define PS0_H  (QS_H + 4 * KV_H)
#define FL_SMEM ((PS0_H + QS_H) * 2)   // 110592 B

__global__ void __launch_bounds__(512, 1) flash_kernel(
    const __half* __restrict__ Q, const __half* __restrict__ K,
    const __half* __restrict__ Vt, __half* __restrict__ Ob)
{
    extern __shared__ __half smh[];

    const int qt  = blockIdx.x;
    const int bh  = blockIdx.y;
    const int b   = bh / HH;
    const int h   = bh - b * HH;
    const int kvh = h / GG;
    const int tid = threadIdx.x;
    const int w   = tid >> 5;
    const int l   = tid & 31;
    const int g   = l >> 2;
    const int t4  = l & 3;

    const __half* qptr  = Q  + (((size_t)b * HH + h) * TT + (size_t)qt * FQ) * HDIM;
    const __half* kptr  = K  + (((size_t)b * KVH + kvh) * TT) * HDIM;
    const __half* vtptr = Vt + (((size_t)b * KVH + kvh) * HDIM) * TT;

    const uint32_t smem_u32 = (uint32_t)__cvta_generic_to_shared(smh);

    const int row_a = (l & 7) + ((l >> 3) & 1) * 8;
    const int ka    = (l >> 4) * 8;
    const uint32_t qa_base = smem_u32 + (uint32_t)(((w * 16 + row_a) * FSH + ka) * 2);
    const uint32_t pa_base = smem_u32 + (uint32_t)((PS0_H + (w * 16 + row_a) * FSH + ka) * 2);
    const int row_b = (l & 7) + ((l >> 4) << 3);
    const int kb_   = ((l >> 3) & 1) * 8;
    const uint32_t b_lane = (uint32_t)((row_b * FSH + kb_) * 2);

    // Q: 256 rows x 8 chunks = 2048
#pragma unroll
    for (int it = 0; it < 4; it++) {
        int idx = tid + it * 512;
        int row = idx >> 3;
        int dq  = idx & 7;
        cp_async16(smem_u32 + (uint32_t)((row * FSH + dq * 8) * 2),
                   &qptr[row * 64 + dq * 8]);
    }
    {
        int row = tid >> 3;       // 0..63
        int dq  = tid & 7;
        cp_async16(smem_u32 + (uint32_t)((KS0_H + row * FSH + dq * 8) * 2),
                   &kptr[(size_t)row * 64 + dq * 8]);
        cp_async16(smem_u32 + (uint32_t)((VS0_H + row * FSH + dq * 8) * 2),
                   &vtptr[(size_t)row * TT + dq * 8]);
        asm volatile("cp.async.commit_group;\n");
    }

    const int r0 = qt * FQ + w * 16 + g;
    const int r1 = r0 + 8;

    float m0 = -1e30f, m1 = -1e30f, l0 = 0.0f, l1 = 0.0f;
    float o[8][4];
#pragma unroll
    for (int nt = 0; nt < 8; nt++)
#pragma unroll
        for (int r = 0; r < 4; r++) o[nt][r] = 0.0f;

    const float scale = 0.125f;
    const int ktmax = 4 * qt + 3;

    for (int kt = 0; kt <= ktmax; kt++) {
        __syncthreads();

        if (kt < ktmax) {
            int nkt = kt + 1;
            uint32_t kb = smem_u32 + (uint32_t)((KS0_H + (nkt & 1) * KV_H) * 2);
            uint32_t vb = smem_u32 + (uint32_t)((VS0_H + (nkt & 1) * KV_H) * 2);
            int row = tid >> 3;
            int dq  = tid & 7;
            cp_async16(kb + (uint32_t)((row * FSH + dq * 8) * 2),
                       &kptr[((size_t)nkt * 64 + row) * 64 + dq * 8]);
            cp_async16(vb + (uint32_t)((row * FSH + dq * 8) * 2),
                       &vtptr[(size_t)row * TT + nkt * 64 + dq * 8]);
            asm volatile("cp.async.commit_group;\n");
            cp_wait<1>();
        } else {
            cp_wait<0>();
        }
        __syncthreads();

        if (kt * 64 > qt * FQ + w * 16 + 15) continue;

        const uint32_t kb_buf = smem_u32 + (uint32_t)((KS0_H + (kt & 1) * KV_H) * 2) + b_lane;
        const uint32_t vb_buf = smem_u32 + (uint32_t)((VS0_H + (kt & 1) * KV_H) * 2) + b_lane;

        // ---- S = Q K^T  (k = d = 64 -> 4 x k16) ----
        float s[8][4];
#pragma unroll
        for (int nt = 0; nt < 8; nt++)
#pragma unroll
            for (int r = 0; r < 4; r++) s[nt][r] = 0.0f;

#pragma unroll
        for (int kp = 0; kp < 4; kp++) {
            uint32_t bf[8][2];
#pragma unroll
            for (int j = 0; j < 4; j++)
                ldsm_x4(bf[2 * j][0], bf[2 * j][1], bf[2 * j + 1][0], bf[2 * j + 1][1],
                        kb_buf + (uint32_t)((j * 16 * FSH + kp * 16) * 2));
            uint32_t a0, a1, a2, a3;
            ldsm_x4(a0, a1, a2, a3, qa_base + (uint32_t)(kp * 16 * 2));
#pragma unroll
            for (int nt = 0; nt < 8; nt++)
                mma_f16(s[nt][0], s[nt][1], s[nt][2], s[nt][3],
                        a0, a1, a2, a3, bf[nt][0], bf[nt][1]);
        }

        // ---- scale + causal mask ----
        if (kt >= 4 * qt) {
            const int kgb = kt * 64 + 2 * t4;
#pragma unroll
            for (int nt = 0; nt < 8; nt++) {
                int kg = kgb + nt * 8;
                s[nt][0] = (kg     > r0) ? -1e30f : s[nt][0] * scale;
                s[nt][1] = (kg + 1 > r0) ? -1e30f : s[nt][1] * scale;
                s[nt][2] = (kg     > r1) ? -1e30f : s[nt][2] * scale;
                s[nt][3] = (kg + 1 > r1) ? -1e30f : s[nt][3] * scale;
            }
        } else {
#pragma unroll
            for (int nt = 0; nt < 8; nt++) {
                s[nt][0] *= scale; s[nt][1] *= scale;
                s[nt][2] *= scale; s[nt][3] *= scale;
            }
        }

        // ---- online softmax ----
        float rm0 = -1e30f, rm1 = -1e30f;
#pragma unroll
        for (int nt = 0; nt < 8; nt++) {
            rm0 = fmaxf(rm0, fmaxf(s[nt][0], s[nt][1]));
            rm1 = fmaxf(rm1, fmaxf(s[nt][2], s[nt][3]));
        }
        rm0 = fmaxf(rm0, __shfl_xor_sync(0xffffffffu, rm0, 1));
        rm0 = fmaxf(rm0, __shfl_xor_sync(0xffffffffu, rm0, 2));
        rm1 = fmaxf(rm1, __shfl_xor_sync(0xffffffffu, rm1, 1));
        rm1 = fmaxf(rm1, __shfl_xor_sync(0xffffffffu, rm1, 2));

        float nm0 = fmaxf(m0, rm0);
        float nm1 = fmaxf(m1, rm1);
        float al0 = __expf(m0 - nm0);
        float al1 = __expf(m1 - nm1);
        m0 = nm0; m1 = nm1;

        __half2 ph[8][2];
        float rs0 = 0.0f, rs1 = 0.0f;
#pragma unroll
        for (int nt = 0; nt < 8; nt++) {
            // round p to fp16; accumulate the ROUNDED values (bias cancels in l)
            __half2 p01 = __floats2half2_rn(__expf(s[nt][0] - nm0), __expf(s[nt][1] - nm0));
            __half2 p23 = __floats2half2_rn(__expf(s[nt][2] - nm1), __expf(s[nt][3] - nm1));
            ph[nt][0] = p01;
            ph[nt][1] = p23;
            float2 f01 = __half22float2(p01);
            float2 f23 = __half22float2(p23);
            rs0 += f01.x + f01.y;
            rs1 += f23.x + f23.y;
        }
        rs0 += __shfl_xor_sync(0xffffffffu, rs0, 1);
        rs0 += __shfl_xor_sync(0xffffffffu, rs0, 2);
        rs1 += __shfl_xor_sync(0xffffffffu, rs1, 1);
        rs1 += __shfl_xor_sync(0xffffffffu, rs1, 2);

        l0 = l0 * al0 + rs0;
        l1 = l1 * al1 + rs1;
#pragma unroll
        for (int nt = 0; nt < 8; nt++) {
            o[nt][0] *= al0; o[nt][1] *= al0;
            o[nt][2] *= al1; o[nt][3] *= al1;
        }

        // ---- store P fp16 (warp-private rows) ----
        __half* Ps = smh + PS0_H;
#pragma unroll
        for (int nt = 0; nt < 8; nt++) {
            *(__half2*)&Ps[(w * 16 + g)     * FSH + nt * 8 + 2 * t4] = ph[nt][0];
            *(__half2*)&Ps[(w * 16 + g + 8) * FSH + nt * 8 + 2 * t4] = ph[nt][1];
        }
        __syncwarp();

        // ---- O += P V  (k = key = 64 -> 4 x k16) ----
#pragma unroll
        for (int kp = 0; kp < 4; kp++) {
            uint32_t bf[8][2];
#pragma unroll
            for (int j = 0; j < 4; j++)
                ldsm_x4(bf[2 * j][0], bf[2 * j][1], bf[2 * j + 1][0], bf[2 * j + 1][1],
                        vb_buf + (uint32_t)((j * 16 * FSH + kp * 16) * 2));
            uint32_t a0, a1, a2, a3;
            ldsm_x4(a0, a1, a2, a3, pa_base + (uint32_t)(kp * 16 * 2));
#pragma unroll
            for (int nt = 0; nt < 8; nt++)
                mma_f16(o[nt][0], o[nt][1], o[nt][2], o[nt][3],
                        a0, a1, a2, a3, bf[nt][0], bf[nt][1]);
        }
    }

    // finalize + fp16 output
    float inv0 = 1.0f / l0;
    float inv1 = 1.0f / l1;
    size_t row0 = (size_t)b * TT + (size_t)qt * FQ + w * 16 + g;
#pragma unroll
    for (int nt = 0; nt < 8; nt++) {
        int col = h * HDIM + nt * 8 + 2 * t4;
        *(__half2*)&Ob[row0 * DD + col] =
            __floats2half2_rn(o[nt][0] * inv0, o[nt][1] * inv0);
        *(__half2*)&Ob[(row0 + 8) * DD + col] =
            __floats2half2_rn(o[nt][2] * inv1, o[nt][3] * inv1);
    }
}

// ---------------------------------------------------------------------------
extern "C" void kernel_launch(void* const* d_in, const int* in_sizes, int n_in,
                              void* d_out, int out_size)
{
    const float* x    = (const float*)d_in[0];
    const float* Wqkv = (const float*)d_in[1];
    const float* Wout = (const float*)d_in[2];
    const float* bout = (const float*)d_in[3];
    const float* rcos = (const float*)d_in[4];
    const float* rsin = (const float*)d_in[5];
    float* out = (float*)d_out;

    float* qkv;
    __half *x16, *wqkvT16, *woutT16, *q16, *k16, *v16, *attn16;
    cudaGetSymbolAddress((void**)&qkv,     g_qkv);
    cudaGetSymbolAddress((void**)&x16,     g_x16);
    cudaGetSymbolAddress((void**)&wqkvT16, g_wqkvT16);
    cudaGetSymbolAddress((void**)&woutT16, g_woutT16);
    cudaGetSymbolAddress((void**)&q16,     g_q16);
    cudaGetSymbolAddress((void**)&k16,     g_k16);
    cudaGetSymbolAddress((void**)&v16,     g_v16);
    cudaGetSymbolAddress((void**)&attn16,  g_attn16);

    // 0. Prep: x -> fp16; weights -> fp16 [N][K]
    round_fp16_kernel<<<1184, 256>>>(x, x16, (MM * DD) / 4);
    transpose_fp16_kernel<<<dim3(NQKV / 32, DD / 32), dim3(32, 8)>>>(Wqkv, wqkvT16, DD, NQKV);
    transpose_fp16_kernel<<<dim3(DD / 32, DD / 32),   dim3(32, 8)>>>(Wout, woutT16, DD, DD);

    const int gemm_smem = 3 * STAGE_H * 2;   // 61440 B

    // 1. QKV projection (fp16 mma, fp32 out)
    {
        cudaFuncSetAttribute(mma_gemm_f16_kernel<0>, cudaFuncAttributeMaxDynamicSharedMemorySize, gemm_smem);
        dim3 grid(NQKV / 128, MM / 128);
        mma_gemm_f16_kernel<0><<<grid, 128, gemm_smem>>>(x16, wqkvT16, qkv, nullptr, MM, NQKV, DD);
    }

    // 2. RoPE + split (fp16 outputs, V transposed)
    {
        int tot = MM * (NQKV / 2);
        rope_split_kernel<<<(tot + 255) / 256, 256>>>(qkv, rcos, rsin, q16, k16, v16);
    }

    // 3. Causal flash attention (fp16 mma)
    {
        cudaFuncSetAttribute(flash_kernel, cudaFuncAttributeMaxDynamicSharedMemorySize, FL_SMEM);
        dim3 grid(TT / FQ, BB * HH);
        flash_kernel<<<grid, 512, FL_SMEM>>>(q16, k16, v16, attn16);
    }

    // 4. Out projection (fp16 mma) + bias + nan_to_num (fp32 out)
    {
        cudaFuncSetAttribute(mma_gemm_f16_kernel<1>, cudaFuncAttributeMaxDynamicSharedMemorySize, gemm_smem);
        dim3 grid(DD / 128, MM / 128);
        mma_gemm_f16_kernel<1><<<grid, 128, gemm_smem>>>(attn16, woutT16, out, bout, MM, DD, DD);
    }
}